// round 1
// baseline (speedup 1.0000x reference)
#include <cuda_runtime.h>

#define NQ   16384
#define NKV  256
#define CH   64
#define MAXB 8

// Scratch (no cudaMalloc allowed)
__device__ float g_xs[MAXB * NKV * CH];
__device__ float g_k [MAXB * NKV * CH];
__device__ float g_v [MAXB * NKV * CH];

// ---------------------------------------------------------------------------
// K1: spatial-reduction conv (8x8, stride 8) == GEMM [2048,4096]x[4096,64]
// block = (batch, oh, co-half): 16 ow tokens x 32 output channels
// smem: one input row slab (128 x 64, pad 65) + Wsr i-slab half (8x64x32)
// ---------------------------------------------------------------------------
#define CONV_SMEM_FLOATS (128 * 65 + 8 * 64 * 32)

__global__ __launch_bounds__(128, 2) void conv_kernel(
    const float* __restrict__ x, const float* __restrict__ Wsr,
    const float* __restrict__ bsr)
{
    extern __shared__ float sm[];
    float*  sXr = sm;                       // 128*65 floats
    float4* sW4 = (float4*)(sm + 128 * 65); // 8*64*8 float4

    const int tid  = threadIdx.x;
    const int half = blockIdx.x & 1;
    const int oh   = (blockIdx.x >> 1) & 15;
    const int b    = blockIdx.x >> 5;
    const int ow   = tid >> 3;   // 0..15
    const int c4   = tid & 7;    // 0..7 -> 4 channels each

    float4 acc = make_float4(0.f, 0.f, 0.f, 0.f);
    const float4* Wg4 = (const float4*)Wsr;

    for (int i = 0; i < 8; i++) {
        __syncthreads();
        const float* xg = x + ((size_t)b * NQ + (size_t)(oh * 8 + i) * 128) * CH;
        for (int idx = tid; idx < 8192; idx += 128)
            sXr[(idx >> 6) * 65 + (idx & 63)] = xg[idx];
        for (int idx = tid; idx < 4096; idx += 128) {
            int jc = idx >> 3;          // j*64 + ci
            int cc = idx & 7;
            sW4[idx] = Wg4[(i * 512 + jc) * 16 + half * 8 + cc];
        }
        __syncthreads();
        for (int j = 0; j < 8; j++) {
            const float*  xp = sXr + (ow * 8 + j) * 65;
            const float4* wp = sW4 + (j * 64) * 8 + c4;
            #pragma unroll 16
            for (int ci = 0; ci < 64; ci++) {
                float  xv = xp[ci];
                float4 w  = wp[ci * 8];
                acc.x += xv * w.x; acc.y += xv * w.y;
                acc.z += xv * w.z; acc.w += xv * w.w;
            }
        }
    }
    const int co = half * 32 + c4 * 4;
    const float4 bb = ((const float4*)bsr)[co >> 2];
    acc.x += bb.x; acc.y += bb.y; acc.z += bb.z; acc.w += bb.w;
    ((float4*)g_xs)[((b * NKV + oh * 16 + ow) * CH + co) >> 2] = acc;
}

// ---------------------------------------------------------------------------
// K2: LayerNorm over conv output + K/V projections. block = 32 tokens.
// ---------------------------------------------------------------------------
__global__ __launch_bounds__(256) void lnkv_kernel(
    const float* __restrict__ gamma, const float* __restrict__ beta,
    const float* __restrict__ Wk, const float* __restrict__ bk,
    const float* __restrict__ Wv, const float* __restrict__ bv)
{
    __shared__ float sA[32 * 65];
    const int tid = threadIdx.x;
    const int tokbase = blockIdx.x * 32;

    for (int idx = tid; idx < 2048; idx += 256)
        sA[(idx >> 6) * 65 + (idx & 63)] = g_xs[(size_t)tokbase * CH + idx];
    __syncthreads();

    if (tid < 32) {
        float* a = sA + tid * 65;
        float mu = 0.f;
        #pragma unroll
        for (int c = 0; c < 64; c++) mu += a[c];
        mu *= (1.0f / 64.0f);
        float var = 0.f;
        #pragma unroll
        for (int c = 0; c < 64; c++) { float d = a[c] - mu; var += d * d; }
        var *= (1.0f / 64.0f);
        float inv = rsqrtf(var + 1e-5f);
        #pragma unroll
        for (int c = 0; c < 64; c++)
            a[c] = (a[c] - mu) * inv * gamma[c] + beta[c];
    }
    __syncthreads();

    const int token = tid >> 3;
    const int c4b   = tid & 7;
    const float*  ar  = sA + token * 65;
    const float4* Wk4 = (const float4*)Wk;
    const float4* Wv4 = (const float4*)Wv;
    #pragma unroll
    for (int of = 0; of < 2; of++) {
        int c4 = c4b + of * 8;
        float4 ka = ((const float4*)bk)[c4];
        float4 va = ((const float4*)bv)[c4];
        for (int j = 0; j < 64; j++) {
            float  av = ar[j];
            float4 wk = Wk4[j * 16 + c4];
            float4 wv = Wv4[j * 16 + c4];
            ka.x += av * wk.x; ka.y += av * wk.y; ka.z += av * wk.z; ka.w += av * wk.w;
            va.x += av * wv.x; va.y += av * wv.y; va.z += av * wv.z; va.w += av * wv.w;
        }
        ((float4*)g_k)[(tokbase + token) * 16 + c4] = ka;
        ((float4*)g_v)[(tokbase + token) * 16 + c4] = va;
    }
}

// ---------------------------------------------------------------------------
// K3: fused q-proj + attention (softmax over 256 kv) + out-proj.
// block = 256 queries of one batch; one thread per query.
// smem: x tile (pad 65), W (Wq then Wp), K tile, V tile.
// ---------------------------------------------------------------------------
#define ATTN_SMEM_FLOATS (256 * 65 + 4096 + 16384 + 16384)

__global__ __launch_bounds__(256, 1) void attn_kernel(
    const float* __restrict__ x,
    const float* __restrict__ Wq, const float* __restrict__ bq,
    const float* __restrict__ Wp, const float* __restrict__ bp,
    float* __restrict__ out)
{
    extern __shared__ float sm[];
    float* sX = sm;                    // 256*65
    float* sW = sm + 256 * 65;         // 4096 (Wq, then Wp)
    float* sK = sW + 4096;             // 16384
    float* sV = sK + 16384;            // 16384

    const int tid   = threadIdx.x;
    const int b     = blockIdx.x >> 6;
    const int tile  = blockIdx.x & 63;
    const int qbase = b * NQ + tile * 256;

    const float* xg = x + (size_t)qbase * CH;
    for (int i = tid; i < 16384; i += 256)
        sX[(i >> 6) * 65 + (i & 63)] = xg[i];
    for (int i = tid; i < 4096; i += 256) sW[i] = Wq[i];
    __syncthreads();

    // q = (x @ Wq + bq) / 8  (fold 1/sqrt(64) into q)
    float q[64];
    #pragma unroll
    for (int c = 0; c < 64; c++) q[c] = bq[c];
    {
        const float*  sxr = sX + tid * 65;
        const float4* w4  = (const float4*)sW;
        for (int j = 0; j < 64; j++) {
            float xv = sxr[j];
            #pragma unroll
            for (int c4 = 0; c4 < 16; c4++) {
                float4 w = w4[j * 16 + c4];
                q[4*c4+0] += xv * w.x; q[4*c4+1] += xv * w.y;
                q[4*c4+2] += xv * w.z; q[4*c4+3] += xv * w.w;
            }
        }
    }
    #pragma unroll
    for (int c = 0; c < 64; c++) q[c] *= 0.125f;
    __syncthreads();   // done with Wq in sW

    const float* kg = g_k + (size_t)b * NKV * CH;
    const float* vg = g_v + (size_t)b * NKV * CH;
    for (int i = tid; i < 16384; i += 256) { sK[i] = kg[i]; sV[i] = vg[i]; }
    for (int i = tid; i < 4096; i += 256) sW[i] = Wp[i];
    __syncthreads();

    // softmax attention (scores are O(1): no-max softmax is exact & safe)
    float o[64];
    #pragma unroll
    for (int c = 0; c < 64; c++) o[c] = 0.f;
    float l = 0.f;
    const float4* k4 = (const float4*)sK;
    const float4* v4 = (const float4*)sV;
    for (int j = 0; j < 256; j++) {
        float s0 = 0.f, s1 = 0.f, s2 = 0.f, s3 = 0.f;
        #pragma unroll
        for (int c4 = 0; c4 < 16; c4++) {
            float4 k = k4[j * 16 + c4];
            s0 += q[4*c4+0] * k.x; s1 += q[4*c4+1] * k.y;
            s2 += q[4*c4+2] * k.z; s3 += q[4*c4+3] * k.w;
        }
        float p = __expf((s0 + s1) + (s2 + s3));
        l += p;
        #pragma unroll
        for (int c4 = 0; c4 < 16; c4++) {
            float4 v = v4[j * 16 + c4];
            o[4*c4+0] += p * v.x; o[4*c4+1] += p * v.y;
            o[4*c4+2] += p * v.z; o[4*c4+3] += p * v.w;
        }
    }

    // stage normalized o through smem (x tile is dead; own row only, no race)
    const float rl = 1.0f / l;
    float* sOr = sX + tid * 65;
    #pragma unroll
    for (int c = 0; c < 64; c++) sOr[c] = o[c] * rl;

    // out-proj: r = o @ Wp + bp
    float r[64];
    #pragma unroll
    for (int c = 0; c < 64; c++) r[c] = bp[c];
    {
        const float4* w4 = (const float4*)sW;
        for (int j = 0; j < 64; j++) {
            float ov = sOr[j];
            #pragma unroll
            for (int c4 = 0; c4 < 16; c4++) {
                float4 w = w4[j * 16 + c4];
                r[4*c4+0] += ov * w.x; r[4*c4+1] += ov * w.y;
                r[4*c4+2] += ov * w.z; r[4*c4+3] += ov * w.w;
            }
        }
    }
    float4* og = (float4*)(out + (size_t)(qbase + tid) * CH);
    #pragma unroll
    for (int c4 = 0; c4 < 16; c4++)
        og[c4] = make_float4(r[4*c4+0], r[4*c4+1], r[4*c4+2], r[4*c4+3]);
}

// ---------------------------------------------------------------------------
extern "C" void kernel_launch(void* const* d_in, const int* in_sizes, int n_in,
                              void* d_out, int out_size)
{
    const float* x     = (const float*)d_in[0];
    const float* Wq    = (const float*)d_in[1];
    const float* bq    = (const float*)d_in[2];
    const float* Wk    = (const float*)d_in[3];
    const float* bk    = (const float*)d_in[4];
    const float* Wv    = (const float*)d_in[5];
    const float* bv    = (const float*)d_in[6];
    const float* Wsr   = (const float*)d_in[7];
    const float* bsr   = (const float*)d_in[8];
    const float* gamma = (const float*)d_in[9];
    const float* beta  = (const float*)d_in[10];
    const float* Wp    = (const float*)d_in[11];
    const float* bp    = (const float*)d_in[12];
    float* out = (float*)d_out;

    int B = in_sizes[0] / (NQ * CH);
    if (B > MAXB) B = MAXB;

    const int conv_smem = CONV_SMEM_FLOATS * 4;   // 98816 B
    const int attn_smem = ATTN_SMEM_FLOATS * 4;   // 214016 B
    cudaFuncSetAttribute(conv_kernel, cudaFuncAttributeMaxDynamicSharedMemorySize, conv_smem);
    cudaFuncSetAttribute(attn_kernel, cudaFuncAttributeMaxDynamicSharedMemorySize, attn_smem);

    conv_kernel<<<B * 32, 128, conv_smem>>>(x, Wsr, bsr);
    lnkv_kernel<<<B * 8, 256>>>(gamma, beta, Wk, bk, Wv, bv);
    attn_kernel<<<B * 64, 256, attn_smem>>>(x, Wq, bq, Wp, bp, out);
}

// round 2
// speedup vs baseline: 1.1344x; 1.1344x over previous
#include <cuda_runtime.h>

#define NQ   16384
#define NKV  256
#define CH   64
#define MAXB 8
#define KSPLIT 4

typedef unsigned long long u64;

__device__ __forceinline__ u64 pack2(float lo, float hi) {
    u64 r; asm("mov.b64 %0, {%1, %2};" : "=l"(r) : "f"(lo), "f"(hi)); return r;
}
__device__ __forceinline__ void unpack2(u64 a, float& lo, float& hi) {
    asm("mov.b64 {%0, %1}, %2;" : "=f"(lo), "=f"(hi) : "l"(a));
}
__device__ __forceinline__ void fma2(u64& d, u64 a, u64 b) {
    asm("fma.rn.f32x2 %0, %1, %2, %0;" : "+l"(d) : "l"(a), "l"(b));
}
__device__ __forceinline__ u64 mul2(u64 a, u64 b) {
    u64 r; asm("mul.rn.f32x2 %0, %1, %2;" : "=l"(r) : "l"(a), "l"(b)); return r;
}

// Scratch (no cudaMalloc allowed)
__device__ float g_part[KSPLIT * MAXB * NKV * CH];   // conv partial sums
__device__ float g_k [MAXB * NKV * CH];
__device__ float g_v [MAXB * NKV * CH];

// ---------------------------------------------------------------------------
// K1: spatial-reduction conv (8x8 stride 8) as K-split GEMM, no smem.
// grid = B * 4(oh-quad) * KSPLIT ; block 256 = 16 ow * 16 co-quads.
// thread = 4 tokens (4 oh rows, same ow) x 4 co -> 8 packed accumulators.
// x: LDG.128 (16-lane broadcast), W: LDG.128 (L1-resident stream).
// ---------------------------------------------------------------------------
__global__ __launch_bounds__(256) void conv_kernel(
    const float* __restrict__ x, const float* __restrict__ Wsr)
{
    const int bi  = blockIdx.x;
    const int ks  = bi & 3;
    const int ohq = (bi >> 2) & 3;
    const int b   = bi >> 4;
    const int g   = threadIdx.x & 15;   // co quad
    const int ow  = threadIdx.x >> 4;   // 0..15

    u64 acc[4][2];
    #pragma unroll
    for (int t = 0; t < 4; t++) { acc[t][0] = 0ull; acc[t][1] = 0ull; }

    #pragma unroll 1
    for (int rr = 0; rr < 2; rr++) {
        const int row = ks * 2 + rr;      // kernel row 0..7
        const float* xt[4];
        #pragma unroll
        for (int t = 0; t < 4; t++) {
            int oh = ohq * 4 + t;
            xt[t] = x + ((size_t)b * NQ + (size_t)(oh * 8 + row) * 128 + ow * 8) * CH;
        }
        #pragma unroll 1
        for (int j = 0; j < 8; j++) {
            const float* wbase = Wsr + (size_t)((row * 8 + j) * CH) * CH + g * 4;
            #pragma unroll 2
            for (int c4 = 0; c4 < 16; c4++) {
                float4 xa[4];
                #pragma unroll
                for (int t = 0; t < 4; t++)
                    xa[t] = __ldg((const float4*)(xt[t] + j * CH + c4 * 4));
                #pragma unroll
                for (int e = 0; e < 4; e++) {
                    float4 w = __ldg((const float4*)(wbase + (size_t)(c4 * 4 + e) * CH));
                    u64 w01 = pack2(w.x, w.y);
                    u64 w23 = pack2(w.z, w.w);
                    #pragma unroll
                    for (int t = 0; t < 4; t++) {
                        float xe = (e == 0) ? xa[t].x : (e == 1) ? xa[t].y
                                 : (e == 2) ? xa[t].z : xa[t].w;
                        u64 xx = pack2(xe, xe);
                        fma2(acc[t][0], xx, w01);
                        fma2(acc[t][1], xx, w23);
                    }
                }
            }
        }
    }

    float* gp = g_part + (size_t)ks * (MAXB * NKV * CH);
    #pragma unroll
    for (int t = 0; t < 4; t++) {
        int tok = b * NKV + (ohq * 4 + t) * 16 + ow;
        float4 r;
        unpack2(acc[t][0], r.x, r.y);
        unpack2(acc[t][1], r.z, r.w);
        *(float4*)(gp + (size_t)tok * CH + g * 4) = r;
    }
}

// ---------------------------------------------------------------------------
// K2: K-split reduction + bias + LayerNorm + K/V projections. block = 32 tokens.
// ---------------------------------------------------------------------------
__global__ __launch_bounds__(256) void lnkv_kernel(
    const float* __restrict__ bsr,
    const float* __restrict__ gamma, const float* __restrict__ beta,
    const float* __restrict__ Wk, const float* __restrict__ bk,
    const float* __restrict__ Wv, const float* __restrict__ bv)
{
    __shared__ float sA[32 * 65];
    const int tid = threadIdx.x;
    const int tokbase = blockIdx.x * 32;

    for (int idx = tid; idx < 2048; idx += 256) {
        size_t off = (size_t)tokbase * CH + idx;
        float v = bsr[idx & 63];
        #pragma unroll
        for (int s = 0; s < KSPLIT; s++)
            v += g_part[(size_t)s * (MAXB * NKV * CH) + off];
        sA[(idx >> 6) * 65 + (idx & 63)] = v;
    }
    __syncthreads();

    if (tid < 32) {
        float* a = sA + tid * 65;
        float mu = 0.f;
        #pragma unroll
        for (int c = 0; c < 64; c++) mu += a[c];
        mu *= (1.0f / 64.0f);
        float var = 0.f;
        #pragma unroll
        for (int c = 0; c < 64; c++) { float d = a[c] - mu; var += d * d; }
        var *= (1.0f / 64.0f);
        float inv = rsqrtf(var + 1e-5f);
        #pragma unroll
        for (int c = 0; c < 64; c++)
            a[c] = (a[c] - mu) * inv * gamma[c] + beta[c];
    }
    __syncthreads();

    const int token = tid >> 3;
    const int c4b   = tid & 7;
    const float* ar = sA + token * 65;
    const float4* Wk4 = (const float4*)Wk;
    const float4* Wv4 = (const float4*)Wv;
    #pragma unroll
    for (int of = 0; of < 2; of++) {
        int c4 = c4b + of * 8;
        float4 ka = ((const float4*)bk)[c4];
        float4 va = ((const float4*)bv)[c4];
        for (int j = 0; j < 64; j++) {
            float  av = ar[j];
            float4 wk = Wk4[j * 16 + c4];
            float4 wv = Wv4[j * 16 + c4];
            ka.x += av * wk.x; ka.y += av * wk.y; ka.z += av * wk.z; ka.w += av * wk.w;
            va.x += av * wv.x; va.y += av * wv.y; va.z += av * wv.z; va.w += av * wv.w;
        }
        ((float4*)g_k)[(tokbase + token) * 16 + c4] = ka;
        ((float4*)g_v)[(tokbase + token) * 16 + c4] = va;
    }
}

// ---------------------------------------------------------------------------
// K3: fused q-proj + attention + out-proj, f32x2 throughout.
// block = 256 queries of one batch; one thread per query.
// ---------------------------------------------------------------------------
#define ATTN_SMEM_FLOATS (256 * 65 + 4096 + 16384 + 16384)

__global__ __launch_bounds__(256, 1) void attn_kernel(
    const float* __restrict__ x,
    const float* __restrict__ Wq, const float* __restrict__ bq,
    const float* __restrict__ Wp, const float* __restrict__ bp,
    float* __restrict__ out)
{
    extern __shared__ float sm[];
    float* sX = sm;                    // 256*65
    float* sW = sm + 256 * 65;         // 4096 (Wq, then Wp)
    float* sK = sW + 4096;             // 16384
    float* sV = sK + 16384;            // 16384

    const int tid   = threadIdx.x;
    const int b     = blockIdx.x >> 6;
    const int tile  = blockIdx.x & 63;
    const int qbase = b * NQ + tile * 256;

    const float* xg = x + (size_t)qbase * CH;
    for (int i = tid; i < 16384; i += 256)
        sX[(i >> 6) * 65 + (i & 63)] = xg[i];
    for (int i = tid; i < 4096; i += 256) sW[i] = Wq[i];
    __syncthreads();

    // q = (x @ Wq + bq) * 0.125   (fold 1/sqrt(64))
    u64 q2[32];
    #pragma unroll
    for (int c2 = 0; c2 < 32; c2++) q2[c2] = ((const u64*)bq)[c2];
    {
        const float* sxr = sX + tid * 65;
        #pragma unroll 2
        for (int j = 0; j < 64; j++) {
            float xv = sxr[j];
            u64 xx = pack2(xv, xv);
            const ulonglong2* wr = (const ulonglong2*)sW + j * 16;
            #pragma unroll
            for (int m = 0; m < 16; m++) {
                ulonglong2 w = wr[m];
                fma2(q2[2 * m + 0], xx, w.x);
                fma2(q2[2 * m + 1], xx, w.y);
            }
        }
    }
    {
        u64 sc = pack2(0.125f, 0.125f);
        #pragma unroll
        for (int c2 = 0; c2 < 32; c2++) q2[c2] = mul2(q2[c2], sc);
    }
    __syncthreads();   // done with Wq in sW

    const float* kg = g_k + (size_t)b * NKV * CH;
    const float* vg = g_v + (size_t)b * NKV * CH;
    for (int i = tid; i < 16384; i += 256) { sK[i] = kg[i]; sV[i] = vg[i]; }
    for (int i = tid; i < 4096; i += 256) sW[i] = Wp[i];
    __syncthreads();

    // softmax attention (scores O(1): no-max softmax is exact & overflow-safe)
    u64 o2[32];
    #pragma unroll
    for (int c2 = 0; c2 < 32; c2++) o2[c2] = 0ull;
    float l = 0.f;

    #pragma unroll 2
    for (int j = 0; j < 256; j++) {
        const ulonglong2* kj = (const ulonglong2*)(sK + j * 64);
        u64 sa = 0ull, sb = 0ull;
        #pragma unroll
        for (int m = 0; m < 16; m += 2) {
            ulonglong2 k0 = kj[m];
            ulonglong2 k1 = kj[m + 1];
            fma2(sa, q2[2 * m + 0], k0.x);
            fma2(sb, q2[2 * m + 1], k0.y);
            fma2(sa, q2[2 * m + 2], k1.x);
            fma2(sb, q2[2 * m + 3], k1.y);
        }
        float a0, a1, b0, b1;
        unpack2(sa, a0, a1); unpack2(sb, b0, b1);
        float p = __expf((a0 + a1) + (b0 + b1));
        l += p;
        u64 pp = pack2(p, p);
        const ulonglong2* vj = (const ulonglong2*)(sV + j * 64);
        #pragma unroll
        for (int m = 0; m < 16; m++) {
            ulonglong2 v = vj[m];
            fma2(o2[2 * m + 0], pp, v.x);
            fma2(o2[2 * m + 1], pp, v.y);
        }
    }

    // out-proj on raw o; fold 1/l into epilogue: r = (o @ Wp) * rl + bp
    u64 t2[32];
    #pragma unroll
    for (int c2 = 0; c2 < 32; c2++) t2[c2] = 0ull;
    #pragma unroll 2
    for (int j2 = 0; j2 < 32; j2++) {
        float oa, ob;
        unpack2(o2[j2], oa, ob);
        u64 aa = pack2(oa, oa);
        u64 bb = pack2(ob, ob);
        const ulonglong2* wa = (const ulonglong2*)sW + (2 * j2) * 16;
        const ulonglong2* wb = (const ulonglong2*)sW + (2 * j2 + 1) * 16;
        #pragma unroll
        for (int m = 0; m < 16; m++) {
            ulonglong2 w0 = wa[m];
            ulonglong2 w1 = wb[m];
            fma2(t2[2 * m + 0], aa, w0.x);
            fma2(t2[2 * m + 1], aa, w0.y);
            fma2(t2[2 * m + 0], bb, w1.x);
            fma2(t2[2 * m + 1], bb, w1.y);
        }
    }

    const float rl = 1.0f / l;
    u64 rlp = pack2(rl, rl);
    ulonglong2* og = (ulonglong2*)(out + (size_t)(qbase + tid) * CH);
    #pragma unroll
    for (int m = 0; m < 16; m++) {
        u64 r0 = ((const u64*)bp)[2 * m + 0];
        u64 r1 = ((const u64*)bp)[2 * m + 1];
        fma2(r0, t2[2 * m + 0], rlp);
        fma2(r1, t2[2 * m + 1], rlp);
        ulonglong2 st; st.x = r0; st.y = r1;
        og[m] = st;
    }
}

// ---------------------------------------------------------------------------
extern "C" void kernel_launch(void* const* d_in, const int* in_sizes, int n_in,
                              void* d_out, int out_size)
{
    const float* x     = (const float*)d_in[0];
    const float* Wq    = (const float*)d_in[1];
    const float* bq    = (const float*)d_in[2];
    const float* Wk    = (const float*)d_in[3];
    const float* bk    = (const float*)d_in[4];
    const float* Wv    = (const float*)d_in[5];
    const float* bv    = (const float*)d_in[6];
    const float* Wsr   = (const float*)d_in[7];
    const float* bsr   = (const float*)d_in[8];
    const float* gamma = (const float*)d_in[9];
    const float* beta  = (const float*)d_in[10];
    const float* Wp    = (const float*)d_in[11];
    const float* bp    = (const float*)d_in[12];
    float* out = (float*)d_out;

    int B = in_sizes[0] / (NQ * CH);
    if (B > MAXB) B = MAXB;

    const int attn_smem = ATTN_SMEM_FLOATS * 4;   // 214016 B
    cudaFuncSetAttribute(attn_kernel, cudaFuncAttributeMaxDynamicSharedMemorySize, attn_smem);

    conv_kernel<<<B * 16, 256>>>(x, Wsr);
    lnkv_kernel<<<B * 8, 256>>>(bsr, gamma, beta, Wk, bk, Wv, bv);
    attn_kernel<<<B * 64, 256, attn_smem>>>(x, Wq, bq, Wp, bp, out);
}

// round 4
// speedup vs baseline: 1.2211x; 1.0764x over previous
#include <cuda_runtime.h>

#define NQ   16384
#define NKV  256
#define CH   64
#define MAXB 8
#define CSPLIT 16

typedef unsigned long long u64;

__device__ __forceinline__ u64 pack2(float lo, float hi) {
    u64 r; asm("mov.b64 %0, {%1, %2};" : "=l"(r) : "f"(lo), "f"(hi)); return r;
}
__device__ __forceinline__ void unpack2(u64 a, float& lo, float& hi) {
    asm("mov.b64 {%0, %1}, %2;" : "=f"(lo), "=f"(hi) : "l"(a));
}
__device__ __forceinline__ void fma2(u64& d, u64 a, u64 b) {
    asm("fma.rn.f32x2 %0, %1, %2, %0;" : "+l"(d) : "l"(a), "l"(b));
}
__device__ __forceinline__ u64 mul2(u64 a, u64 b) {
    u64 r; asm("mul.rn.f32x2 %0, %1, %2;" : "=l"(r) : "l"(a), "l"(b)); return r;
}

// Scratch (no cudaMalloc allowed)
__device__ float g_part[CSPLIT * MAXB * NKV * CH];   // conv partial sums
__device__ float g_k [MAXB * NKV * CH];
__device__ float g_v [MAXB * NKV * CH];

// ---------------------------------------------------------------------------
// K1: spatial-reduction conv (8x8 stride 8) as K-split GEMM.
// K dim = 64 positions x 64 ci. Split = 4 consecutive positions (same kernel
// row i, 4 consecutive j) -> weight slab is 64KB CONTIGUOUS in Wsr (HWIO).
// block = 128 tokens x 1 split; thread = 1 token, 64 co in 32 f32x2 accs.
// W slab in smem (broadcast LDS), x = 1KB contiguous per thread (L1).
// ---------------------------------------------------------------------------
__global__ __launch_bounds__(128) void conv_kernel(
    const float* __restrict__ x, const float* __restrict__ Wsr)
{
    extern __shared__ float sW[];   // 4*64*64 floats = 64KB
    const int tid   = threadIdx.x;
    const int split = blockIdx.x & 15;
    const int tile  = blockIdx.x >> 4;

    // load weight slab (contiguous 16384 floats)
    {
        const float4* wg = (const float4*)(Wsr + (size_t)split * 16384);
        float4* sw4 = (float4*)sW;
        #pragma unroll
        for (int k = 0; k < 32; k++) sw4[k * 128 + tid] = wg[k * 128 + tid];
    }
    __syncthreads();

    const int token = tile * 128 + tid;
    const int b  = token >> 8;
    const int rm = token & 255;
    const int oh = rm >> 4;
    const int ow = rm & 15;
    const int i  = split >> 1;
    const int j0 = (split & 1) * 4;
    const float* xb = x + ((size_t)b * NQ + (size_t)(oh * 8 + i) * 128 + (ow * 8 + j0)) * CH;

    u64 acc[32];
    #pragma unroll
    for (int m = 0; m < 32; m++) acc[m] = 0ull;

    #pragma unroll
    for (int p = 0; p < 4; p++) {
        const float4*     xp = (const float4*)(xb + p * CH);
        const ulonglong2* wp = (const ulonglong2*)(sW + p * 64 * 64);
        #pragma unroll 2
        for (int c4 = 0; c4 < 16; c4++) {
            float4 xa = __ldg(xp + c4);
            #pragma unroll
            for (int e = 0; e < 4; e++) {
                float xe = (e == 0) ? xa.x : (e == 1) ? xa.y : (e == 2) ? xa.z : xa.w;
                u64 xx = pack2(xe, xe);
                const ulonglong2* wr = wp + (c4 * 4 + e) * 16;   // row = 64 co = 16 u64x2
                #pragma unroll
                for (int m = 0; m < 16; m++) {
                    ulonglong2 w = wr[m];
                    fma2(acc[2 * m + 0], xx, w.x);
                    fma2(acc[2 * m + 1], xx, w.y);
                }
            }
        }
    }

    float4* gp = (float4*)(g_part + ((size_t)split * (MAXB * NKV) + token) * CH);
    #pragma unroll
    for (int m = 0; m < 8; m++) {
        float4 r0, r1;
        unpack2(acc[4 * m + 0], r0.x, r0.y);
        unpack2(acc[4 * m + 1], r0.z, r0.w);
        unpack2(acc[4 * m + 2], r1.x, r1.y);
        unpack2(acc[4 * m + 3], r1.z, r1.w);
        gp[2 * m + 0] = r0;
        gp[2 * m + 1] = r1;
    }
}

// ---------------------------------------------------------------------------
// K2: K-split reduction + bias + LayerNorm + K/V projections. block = 32 tokens.
// ---------------------------------------------------------------------------
__global__ __launch_bounds__(256) void lnkv_kernel(
    const float* __restrict__ bsr,
    const float* __restrict__ gamma, const float* __restrict__ beta,
    const float* __restrict__ Wk, const float* __restrict__ bk,
    const float* __restrict__ Wv, const float* __restrict__ bv)
{
    __shared__ float sA[32 * 65];
    const int tid = threadIdx.x;
    const int tokbase = blockIdx.x * 32;

    for (int idx = tid; idx < 2048; idx += 256) {
        size_t off = (size_t)tokbase * CH + idx;
        float v = bsr[idx & 63];
        #pragma unroll
        for (int s = 0; s < CSPLIT; s++)
            v += g_part[(size_t)s * (MAXB * NKV * CH) + off];
        sA[(idx >> 6) * 65 + (idx & 63)] = v;
    }
    __syncthreads();

    if (tid < 32) {
        float* a = sA + tid * 65;
        float mu = 0.f;
        #pragma unroll
        for (int c = 0; c < 64; c++) mu += a[c];
        mu *= (1.0f / 64.0f);
        float var = 0.f;
        #pragma unroll
        for (int c = 0; c < 64; c++) { float d = a[c] - mu; var += d * d; }
        var *= (1.0f / 64.0f);
        float inv = rsqrtf(var + 1e-5f);
        #pragma unroll
        for (int c = 0; c < 64; c++)
            a[c] = (a[c] - mu) * inv * gamma[c] + beta[c];
    }
    __syncthreads();

    const int token = tid >> 3;
    const int c4b   = tid & 7;
    const float* ar = sA + token * 65;
    const float4* Wk4 = (const float4*)Wk;
    const float4* Wv4 = (const float4*)Wv;
    #pragma unroll
    for (int of = 0; of < 2; of++) {
        int c4 = c4b + of * 8;
        float4 ka = ((const float4*)bk)[c4];
        float4 va = ((const float4*)bv)[c4];
        for (int j = 0; j < 64; j++) {
            float  av = ar[j];
            float4 wk = Wk4[j * 16 + c4];
            float4 wv = Wv4[j * 16 + c4];
            ka.x += av * wk.x; ka.y += av * wk.y; ka.z += av * wk.z; ka.w += av * wk.w;
            va.x += av * wv.x; va.y += av * wv.y; va.z += av * wv.z; va.w += av * wv.w;
        }
        ((float4*)g_k)[(tokbase + token) * 16 + c4] = ka;
        ((float4*)g_v)[(tokbase + token) * 16 + c4] = va;
    }
}

// ---------------------------------------------------------------------------
// K3: fused q-proj + attention + out-proj, f32x2 throughout.
// block = 256 queries of one batch; one thread per query.  (unchanged)
// ---------------------------------------------------------------------------
#define ATTN_SMEM_FLOATS (256 * 65 + 4096 + 16384 + 16384)

__global__ __launch_bounds__(256, 1) void attn_kernel(
    const float* __restrict__ x,
    const float* __restrict__ Wq, const float* __restrict__ bq,
    const float* __restrict__ Wp, const float* __restrict__ bp,
    float* __restrict__ out)
{
    extern __shared__ float sm[];
    float* sX = sm;                    // 256*65
    float* sW = sm + 256 * 65;         // 4096 (Wq, then Wp)
    float* sK = sW + 4096;             // 16384
    float* sV = sK + 16384;            // 16384

    const int tid   = threadIdx.x;
    const int b     = blockIdx.x >> 6;
    const int tile  = blockIdx.x & 63;
    const int qbase = b * NQ + tile * 256;

    const float* xg = x + (size_t)qbase * CH;
    for (int i = tid; i < 16384; i += 256)
        sX[(i >> 6) * 65 + (i & 63)] = xg[i];
    for (int i = tid; i < 4096; i += 256) sW[i] = Wq[i];
    __syncthreads();

    // q = (x @ Wq + bq) * 0.125   (fold 1/sqrt(64))
    u64 q2[32];
    #pragma unroll
    for (int c2 = 0; c2 < 32; c2++) q2[c2] = ((const u64*)bq)[c2];
    {
        const float* sxr = sX + tid * 65;
        #pragma unroll 2
        for (int j = 0; j < 64; j++) {
            float xv = sxr[j];
            u64 xx = pack2(xv, xv);
            const ulonglong2* wr = (const ulonglong2*)sW + j * 16;
            #pragma unroll
            for (int m = 0; m < 16; m++) {
                ulonglong2 w = wr[m];
                fma2(q2[2 * m + 0], xx, w.x);
                fma2(q2[2 * m + 1], xx, w.y);
            }
        }
    }
    {
        u64 sc = pack2(0.125f, 0.125f);
        #pragma unroll
        for (int c2 = 0; c2 < 32; c2++) q2[c2] = mul2(q2[c2], sc);
    }
    __syncthreads();   // done with Wq in sW

    const float* kg = g_k + (size_t)b * NKV * CH;
    const float* vg = g_v + (size_t)b * NKV * CH;
    for (int i = tid; i < 16384; i += 256) { sK[i] = kg[i]; sV[i] = vg[i]; }
    for (int i = tid; i < 4096; i += 256) sW[i] = Wp[i];
    __syncthreads();

    // softmax attention (scores O(1): no-max softmax is exact & overflow-safe)
    u64 o2[32];
    #pragma unroll
    for (int c2 = 0; c2 < 32; c2++) o2[c2] = 0ull;
    float l = 0.f;

    #pragma unroll 2
    for (int j = 0; j < 256; j++) {
        const ulonglong2* kj = (const ulonglong2*)(sK + j * 64);
        u64 sa = 0ull, sb = 0ull;
        #pragma unroll
        for (int m = 0; m < 16; m += 2) {
            ulonglong2 k0 = kj[m];
            ulonglong2 k1 = kj[m + 1];
            fma2(sa, q2[2 * m + 0], k0.x);
            fma2(sb, q2[2 * m + 1], k0.y);
            fma2(sa, q2[2 * m + 2], k1.x);
            fma2(sb, q2[2 * m + 3], k1.y);
        }
        float a0, a1, b0, b1;
        unpack2(sa, a0, a1); unpack2(sb, b0, b1);
        float p = __expf((a0 + a1) + (b0 + b1));
        l += p;
        u64 pp = pack2(p, p);
        const ulonglong2* vj = (const ulonglong2*)(sV + j * 64);
        #pragma unroll
        for (int m = 0; m < 16; m++) {
            ulonglong2 v = vj[m];
            fma2(o2[2 * m + 0], pp, v.x);
            fma2(o2[2 * m + 1], pp, v.y);
        }
    }

    // out-proj on raw o; fold 1/l into epilogue: r = (o @ Wp) * rl + bp
    u64 t2[32];
    #pragma unroll
    for (int c2 = 0; c2 < 32; c2++) t2[c2] = 0ull;
    #pragma unroll 2
    for (int j2 = 0; j2 < 32; j2++) {
        float oa, ob;
        unpack2(o2[j2], oa, ob);
        u64 aa = pack2(oa, oa);
        u64 bb = pack2(ob, ob);
        const ulonglong2* wa = (const ulonglong2*)sW + (2 * j2) * 16;
        const ulonglong2* wb = (const ulonglong2*)sW + (2 * j2 + 1) * 16;
        #pragma unroll
        for (int m = 0; m < 16; m++) {
            ulonglong2 w0 = wa[m];
            ulonglong2 w1 = wb[m];
            fma2(t2[2 * m + 0], aa, w0.x);
            fma2(t2[2 * m + 1], aa, w0.y);
            fma2(t2[2 * m + 0], bb, w1.x);
            fma2(t2[2 * m + 1], bb, w1.y);
        }
    }

    const float rl = 1.0f / l;
    u64 rlp = pack2(rl, rl);
    ulonglong2* og = (ulonglong2*)(out + (size_t)(qbase + tid) * CH);
    #pragma unroll
    for (int m = 0; m < 16; m++) {
        u64 r0 = ((const u64*)bp)[2 * m + 0];
        u64 r1 = ((const u64*)bp)[2 * m + 1];
        fma2(r0, t2[2 * m + 0], rlp);
        fma2(r1, t2[2 * m + 1], rlp);
        ulonglong2 st; st.x = r0; st.y = r1;
        og[m] = st;
    }
}

// ---------------------------------------------------------------------------
extern "C" void kernel_launch(void* const* d_in, const int* in_sizes, int n_in,
                              void* d_out, int out_size)
{
    const float* x     = (const float*)d_in[0];
    const float* Wq    = (const float*)d_in[1];
    const float* bq    = (const float*)d_in[2];
    const float* Wk    = (const float*)d_in[3];
    const float* bk    = (const float*)d_in[4];
    const float* Wv    = (const float*)d_in[5];
    const float* bv    = (const float*)d_in[6];
    const float* Wsr   = (const float*)d_in[7];
    const float* bsr   = (const float*)d_in[8];
    const float* gamma = (const float*)d_in[9];
    const float* beta  = (const float*)d_in[10];
    const float* Wp    = (const float*)d_in[11];
    const float* bp    = (const float*)d_in[12];
    float* out = (float*)d_out;

    int B = in_sizes[0] / (NQ * CH);
    if (B > MAXB) B = MAXB;

    const int conv_smem = 4 * 64 * 64 * 4;        // 65536 B
    const int attn_smem = ATTN_SMEM_FLOATS * 4;   // 214016 B
    cudaFuncSetAttribute(conv_kernel, cudaFuncAttributeMaxDynamicSharedMemorySize, conv_smem);
    cudaFuncSetAttribute(attn_kernel, cudaFuncAttributeMaxDynamicSharedMemorySize, attn_smem);

    conv_kernel<<<B * 2 * CSPLIT, 128, conv_smem>>>(x, Wsr);
    lnkv_kernel<<<B * 8, 256>>>(bsr, gamma, beta, Wk, bk, Wv, bv);
    attn_kernel<<<B * 64, 256, attn_smem>>>(x, Wq, bq, Wp, bp, out);
}

// round 6
// speedup vs baseline: 2.8260x; 2.3143x over previous
#include <cuda_runtime.h>
#include <cuda_fp16.h>
#include <mma.h>

using namespace nvcuda;

#define NQ   16384
#define NKV  256
#define CH   64
#define MAXB 8
#define CSPLIT 16

typedef unsigned long long u64;
typedef unsigned int u32;

__device__ __forceinline__ u64 pack2(float lo, float hi) {
    u64 r; asm("mov.b64 %0, {%1, %2};" : "=l"(r) : "f"(lo), "f"(hi)); return r;
}
__device__ __forceinline__ void unpack2(u64 a, float& lo, float& hi) {
    asm("mov.b64 {%0, %1}, %2;" : "=f"(lo), "=f"(hi) : "l"(a));
}
__device__ __forceinline__ void fma2(u64& d, u64 a, u64 b) {
    asm("fma.rn.f32x2 %0, %1, %2, %0;" : "+l"(d) : "l"(a), "l"(b));
}

// Scratch (no cudaMalloc allowed)
__device__ float  g_part[CSPLIT * MAXB * NKV * CH];   // conv partial sums
__device__ __half g_kh [MAXB * NKV * CH];             // K fp16 [tok][ch]
__device__ __half g_vh [MAXB * NKV * CH];             // V fp16 [tok][ch]

// ---------------------------------------------------------------------------
// K1: spatial-reduction conv (8x8 stride 8) as K-split GEMM. (unchanged)
// ---------------------------------------------------------------------------
__global__ __launch_bounds__(128) void conv_kernel(
    const float* __restrict__ x, const float* __restrict__ Wsr)
{
    extern __shared__ float sW[];   // 4*64*64 floats = 64KB
    const int tid   = threadIdx.x;
    const int split = blockIdx.x & 15;
    const int tile  = blockIdx.x >> 4;

    {
        const float4* wg = (const float4*)(Wsr + (size_t)split * 16384);
        float4* sw4 = (float4*)sW;
        #pragma unroll
        for (int k = 0; k < 32; k++) sw4[k * 128 + tid] = wg[k * 128 + tid];
    }
    __syncthreads();

    const int token = tile * 128 + tid;
    const int b  = token >> 8;
    const int rm = token & 255;
    const int oh = rm >> 4;
    const int ow = rm & 15;
    const int i  = split >> 1;
    const int j0 = (split & 1) * 4;
    const float* xb = x + ((size_t)b * NQ + (size_t)(oh * 8 + i) * 128 + (ow * 8 + j0)) * CH;

    u64 acc[32];
    #pragma unroll
    for (int m = 0; m < 32; m++) acc[m] = 0ull;

    #pragma unroll
    for (int p = 0; p < 4; p++) {
        const float4*     xp = (const float4*)(xb + p * CH);
        const ulonglong2* wp = (const ulonglong2*)(sW + p * 64 * 64);
        #pragma unroll 2
        for (int c4 = 0; c4 < 16; c4++) {
            float4 xa = __ldg(xp + c4);
            #pragma unroll
            for (int e = 0; e < 4; e++) {
                float xe = (e == 0) ? xa.x : (e == 1) ? xa.y : (e == 2) ? xa.z : xa.w;
                u64 xx = pack2(xe, xe);
                const ulonglong2* wr = wp + (c4 * 4 + e) * 16;
                #pragma unroll
                for (int m = 0; m < 16; m++) {
                    ulonglong2 w = wr[m];
                    fma2(acc[2 * m + 0], xx, w.x);
                    fma2(acc[2 * m + 1], xx, w.y);
                }
            }
        }
    }

    float4* gp = (float4*)(g_part + ((size_t)split * (MAXB * NKV) + token) * CH);
    #pragma unroll
    for (int m = 0; m < 8; m++) {
        float4 r0, r1;
        unpack2(acc[4 * m + 0], r0.x, r0.y);
        unpack2(acc[4 * m + 1], r0.z, r0.w);
        unpack2(acc[4 * m + 2], r1.x, r1.y);
        unpack2(acc[4 * m + 3], r1.z, r1.w);
        gp[2 * m + 0] = r0;
        gp[2 * m + 1] = r1;
    }
}

// ---------------------------------------------------------------------------
// K2: K-split reduce + bias + LayerNorm + K/V proj -> fp16 K, V (row-major).
// ---------------------------------------------------------------------------
__global__ __launch_bounds__(256) void lnkv_kernel(
    const float* __restrict__ bsr,
    const float* __restrict__ gamma, const float* __restrict__ beta,
    const float* __restrict__ Wk, const float* __restrict__ bk,
    const float* __restrict__ Wv, const float* __restrict__ bv)
{
    __shared__ float sA[32 * 65];
    const int tid = threadIdx.x;
    const int tokbase = blockIdx.x * 32;

    for (int idx = tid; idx < 2048; idx += 256) {
        size_t off = (size_t)tokbase * CH + idx;
        float v = bsr[idx & 63];
        #pragma unroll
        for (int s = 0; s < CSPLIT; s++)
            v += g_part[(size_t)s * (MAXB * NKV * CH) + off];
        sA[(idx >> 6) * 65 + (idx & 63)] = v;
    }
    __syncthreads();

    if (tid < 32) {
        float* a = sA + tid * 65;
        float mu = 0.f;
        #pragma unroll
        for (int c = 0; c < 64; c++) mu += a[c];
        mu *= (1.0f / 64.0f);
        float var = 0.f;
        #pragma unroll
        for (int c = 0; c < 64; c++) { float d = a[c] - mu; var += d * d; }
        var *= (1.0f / 64.0f);
        float inv = rsqrtf(var + 1e-5f);
        #pragma unroll
        for (int c = 0; c < 64; c++)
            a[c] = (a[c] - mu) * inv * gamma[c] + beta[c];
    }
    __syncthreads();

    const int token = tid >> 3;
    const int c4b   = tid & 7;
    const float* ar = sA + token * 65;
    const float4* Wk4 = (const float4*)Wk;
    const float4* Wv4 = (const float4*)Wv;
    const int gtok = tokbase + token;
    #pragma unroll
    for (int of = 0; of < 2; of++) {
        int c4 = c4b + of * 8;
        float4 ka = ((const float4*)bk)[c4];
        float4 va = ((const float4*)bv)[c4];
        for (int j = 0; j < 64; j++) {
            float  av = ar[j];
            float4 wk = Wk4[j * 16 + c4];
            float4 wv = Wv4[j * 16 + c4];
            ka.x += av * wk.x; ka.y += av * wk.y; ka.z += av * wk.z; ka.w += av * wk.w;
            va.x += av * wv.x; va.y += av * wv.y; va.z += av * wv.z; va.w += av * wv.w;
        }
        __half2* kp = (__half2*)(g_kh + (size_t)gtok * CH + c4 * 4);
        kp[0] = __floats2half2_rn(ka.x, ka.y);
        kp[1] = __floats2half2_rn(ka.z, ka.w);
        __half2* vp = (__half2*)(g_vh + (size_t)gtok * CH + c4 * 4);
        vp[0] = __floats2half2_rn(va.x, va.y);
        vp[1] = __floats2half2_rn(va.z, va.w);
    }
}

// ---------------------------------------------------------------------------
// K3: wmma (HMMA) fused attention. CTA = 128 queries, 8 warps (16 rows each).
// fp16 operands, fp32 accumulate. One __syncthreads; rest warp-local.
// ---------------------------------------------------------------------------
// smem layout (halves stride 72 = 144B rows; P stride 264; scratch f32 stride 20)
#define SM_K    0            // K  [256][72] fp16  36864B
#define SM_V    36864        // V  [256][72] fp16  36864B
#define SM_X    73728        // X->Q->O [128][72] fp16  18432B
#define SM_WQ   92160        // Wq [64][72] fp16  9216B
#define SM_WP   101376       // Wp [64][72] fp16  9216B
#define SM_P    110592       // P  [128][264] fp16  67584B
#define SM_SCR  178176       // scratch 8 warps x 16x20 f32  10240B
#define SM_TOTAL 188416

__global__ __launch_bounds__(256, 1) void attn_kernel(
    const float* __restrict__ x,
    const float* __restrict__ Wq, const float* __restrict__ bq,
    const float* __restrict__ Wp, const float* __restrict__ bp,
    float* __restrict__ out)
{
    extern __shared__ char smem[];
    __half* sK  = (__half*)(smem + SM_K);
    __half* sV  = (__half*)(smem + SM_V);
    __half* sX  = (__half*)(smem + SM_X);
    __half* sWQ = (__half*)(smem + SM_WQ);
    __half* sWP = (__half*)(smem + SM_WP);
    __half* sP  = (__half*)(smem + SM_P);

    const int tid = threadIdx.x;
    const int wid = tid >> 5;
    const int lid = tid & 31;
    const int row16 = lid & 15;          // lane's row within warp tile
    const int half8 = (lid >> 4) * 8;    // lane's col offset (0 or 8)
    const int wrow = wid * 16;           // warp's first row

    const int b = blockIdx.x >> 7;
    const int qbase = blockIdx.x * 128;

    float* scr = (float*)(smem + SM_SCR) + wid * 320;   // 16 x 20 f32

    // ---- stage: X (fp32->fp16) ----
    {
        const float4* xs = (const float4*)(x + (size_t)qbase * CH);
        #pragma unroll
        for (int it = 0; it < 8; it++) {
            int idx = tid + it * 256;         // float4 id, 2048 total
            int row = idx >> 4, c4 = idx & 15;
            float4 f = __ldg(xs + idx);
            __half2* d = (__half2*)(sX + row * 72 + c4 * 4);
            d[0] = __floats2half2_rn(f.x, f.y);
            d[1] = __floats2half2_rn(f.z, f.w);
        }
    }
    // ---- stage: K, V (fp16 copies) ----
    {
        const uint4* ks = (const uint4*)(g_kh + (size_t)b * NKV * CH);
        const uint4* vs = (const uint4*)(g_vh + (size_t)b * NKV * CH);
        #pragma unroll
        for (int it = 0; it < 8; it++) {
            int idx = tid + it * 256;         // 16B chunk, 2048 total
            int row = idx >> 3, sub = idx & 7;
            *(uint4*)(sK + row * 72 + sub * 8) = __ldg(ks + idx);
            *(uint4*)(sV + row * 72 + sub * 8) = __ldg(vs + idx);
        }
    }
    // ---- stage: Wq, Wp (fp32->fp16, row-major [k][n]) ----
    {
        #pragma unroll
        for (int it = 0; it < 8; it++) {
            int idx = tid + it * 256;         // float4 id, 2048 total
            int sel = idx >> 10;
            int r   = (idx >> 4) & 63, c4 = idx & 15;
            const float4* src = (const float4*)(sel ? Wp : Wq);
            __half* dst = sel ? sWP : sWQ;
            float4 f = __ldg(src + (idx & 1023));
            __half2* d = (__half2*)(dst + r * 72 + c4 * 4);
            d[0] = __floats2half2_rn(f.x, f.y);
            d[1] = __floats2half2_rn(f.z, f.w);
        }
    }
    __syncthreads();

    // ---- GEMM1: Q = (X @ Wq + bq) * 0.125 ----
    wmma::fragment<wmma::matrix_a, 16, 16, 16, __half, wmma::row_major> aX[4];
    #pragma unroll
    for (int k = 0; k < 4; k++)
        wmma::load_matrix_sync(aX[k], sX + wrow * 72 + k * 16, 72);

    #pragma unroll 1
    for (int n = 0; n < 4; n++) {
        wmma::fragment<wmma::accumulator, 16, 16, 16, float> c;
        wmma::fill_fragment(c, 0.0f);
        #pragma unroll
        for (int k = 0; k < 4; k++) {
            wmma::fragment<wmma::matrix_b, 16, 16, 16, __half, wmma::row_major> bw;
            wmma::load_matrix_sync(bw, sWQ + k * 16 * 72 + n * 16, 72);
            wmma::mma_sync(c, aX[k], bw, c);
        }
        wmma::store_matrix_sync(scr, c, 20, wmma::mem_row_major);
        __syncwarp();
        #pragma unroll
        for (int e = 0; e < 8; e++) {
            int col = n * 16 + half8 + e;
            float v = (scr[row16 * 20 + half8 + e] + __ldg(bq + col)) * 0.125f;
            sX[(wrow + row16) * 72 + col] = __float2half_rn(v);
        }
        __syncwarp();
    }

    // ---- GEMM2 + softmax: P = exp(Q @ K^T), l = rowsum ----
    wmma::fragment<wmma::matrix_a, 16, 16, 16, __half, wmma::row_major> aQ[4];
    #pragma unroll
    for (int k = 0; k < 4; k++)
        wmma::load_matrix_sync(aQ[k], sX + wrow * 72 + k * 16, 72);

    float lsum = 0.f;
    #pragma unroll 1
    for (int n = 0; n < 16; n++) {
        wmma::fragment<wmma::accumulator, 16, 16, 16, float> c;
        wmma::fill_fragment(c, 0.0f);
        #pragma unroll
        for (int k = 0; k < 4; k++) {
            wmma::fragment<wmma::matrix_b, 16, 16, 16, __half, wmma::col_major> bk_;
            wmma::load_matrix_sync(bk_, sK + n * 16 * 72 + k * 16, 72);
            wmma::mma_sync(c, aQ[k], bk_, c);
        }
        wmma::store_matrix_sync(scr, c, 20, wmma::mem_row_major);
        __syncwarp();
        #pragma unroll
        for (int e = 0; e < 8; e++) {
            float ev = __expf(scr[row16 * 20 + half8 + e]);
            lsum += ev;
            sP[(wrow + row16) * 264 + n * 16 + half8 + e] = __float2half_rn(ev);
        }
        __syncwarp();
    }
    lsum += __shfl_xor_sync(0xffffffffu, lsum, 16);
    const float rl = 1.0f / lsum;

    // ---- GEMM3: O = (P @ V) * rl ----
    {
        wmma::fragment<wmma::accumulator, 16, 16, 16, float> co[4];
        #pragma unroll
        for (int n = 0; n < 4; n++) wmma::fill_fragment(co[n], 0.0f);
        #pragma unroll 1
        for (int k = 0; k < 16; k++) {
            wmma::fragment<wmma::matrix_a, 16, 16, 16, __half, wmma::row_major> aP;
            wmma::load_matrix_sync(aP, sP + wrow * 264 + k * 16, 264);
            #pragma unroll
            for (int n = 0; n < 4; n++) {
                wmma::fragment<wmma::matrix_b, 16, 16, 16, __half, wmma::row_major> bv_;
                wmma::load_matrix_sync(bv_, sV + k * 16 * 72 + n * 16, 72);
                wmma::mma_sync(co[n], aP, bv_, co[n]);
            }
        }
        #pragma unroll 1
        for (int n = 0; n < 4; n++) {
            wmma::store_matrix_sync(scr, co[n], 20, wmma::mem_row_major);
            __syncwarp();
            #pragma unroll
            for (int e = 0; e < 8; e++) {
                float v = scr[row16 * 20 + half8 + e] * rl;
                sX[(wrow + row16) * 72 + n * 16 + half8 + e] = __float2half_rn(v);
            }
            __syncwarp();
        }
    }

    // ---- GEMM4: Y = O @ Wp + bp -> gmem ----
    wmma::fragment<wmma::matrix_a, 16, 16, 16, __half, wmma::row_major> aO[4];
    #pragma unroll
    for (int k = 0; k < 4; k++)
        wmma::load_matrix_sync(aO[k], sX + wrow * 72 + k * 16, 72);

    #pragma unroll 1
    for (int n = 0; n < 4; n++) {
        wmma::fragment<wmma::accumulator, 16, 16, 16, float> c;
        wmma::fill_fragment(c, 0.0f);
        #pragma unroll
        for (int k = 0; k < 4; k++) {
            wmma::fragment<wmma::matrix_b, 16, 16, 16, __half, wmma::row_major> bw;
            wmma::load_matrix_sync(bw, sWP + k * 16 * 72 + n * 16, 72);
            wmma::mma_sync(c, aO[k], bw, c);
        }
        wmma::store_matrix_sync(scr, c, 20, wmma::mem_row_major);
        __syncwarp();
        #pragma unroll
        for (int e = 0; e < 8; e++) {
            int col = n * 16 + half8 + e;
            out[(size_t)(qbase + wrow + row16) * CH + col] =
                scr[row16 * 20 + half8 + e] + __ldg(bp + col);
        }
        __syncwarp();
    }
}

// ---------------------------------------------------------------------------
extern "C" void kernel_launch(void* const* d_in, const int* in_sizes, int n_in,
                              void* d_out, int out_size)
{
    const float* x     = (const float*)d_in[0];
    const float* Wq    = (const float*)d_in[1];
    const float* bq    = (const float*)d_in[2];
    const float* Wk    = (const float*)d_in[3];
    const float* bk    = (const float*)d_in[4];
    const float* Wv    = (const float*)d_in[5];
    const float* bv    = (const float*)d_in[6];
    const float* Wsr   = (const float*)d_in[7];
    const float* bsr   = (const float*)d_in[8];
    const float* gamma = (const float*)d_in[9];
    const float* beta  = (const float*)d_in[10];
    const float* Wp    = (const float*)d_in[11];
    const float* bp    = (const float*)d_in[12];
    float* out = (float*)d_out;

    int B = in_sizes[0] / (NQ * CH);
    if (B > MAXB) B = MAXB;

    const int conv_smem = 4 * 64 * 64 * 4;        // 65536 B
    cudaFuncSetAttribute(conv_kernel, cudaFuncAttributeMaxDynamicSharedMemorySize, conv_smem);
    cudaFuncSetAttribute(attn_kernel, cudaFuncAttributeMaxDynamicSharedMemorySize, SM_TOTAL);

    conv_kernel<<<B * 2 * CSPLIT, 128, conv_smem>>>(x, Wsr);
    lnkv_kernel<<<B * 8, 256>>>(bsr, gamma, beta, Wk, bk, Wv, bv);
    attn_kernel<<<B * 128, 256, SM_TOTAL>>>(x, Wq, bq, Wp, bp, out);
}

// round 7
// speedup vs baseline: 5.3029x; 1.8765x over previous
#include <cuda_runtime.h>
#include <cuda_fp16.h>

#define NQ   16384
#define NKV  256
#define CH   64
#define MAXB 8
#define CSPLIT 32

typedef unsigned long long u64;
typedef unsigned int u32;

__device__ __forceinline__ u64 pack2(float lo, float hi) {
    u64 r; asm("mov.b64 %0, {%1, %2};" : "=l"(r) : "f"(lo), "f"(hi)); return r;
}
__device__ __forceinline__ void unpack2(u64 a, float& lo, float& hi) {
    asm("mov.b64 {%0, %1}, %2;" : "=f"(lo), "=f"(hi) : "l"(a));
}
__device__ __forceinline__ void fma2(u64& d, u64 a, u64 b) {
    asm("fma.rn.f32x2 %0, %1, %2, %0;" : "+l"(d) : "l"(a), "l"(b));
}
__device__ __forceinline__ u32 pack_h2(float lo, float hi) {
    u32 r; asm("cvt.rn.f16x2.f32 %0, %1, %2;" : "=r"(r) : "f"(hi), "f"(lo)); return r;
}
__device__ __forceinline__ u32 smem_u32(const void* p) {
    u32 a; asm("{ .reg .u64 t; cvta.to.shared.u64 t, %1; cvt.u32.u64 %0, t; }" : "=r"(a) : "l"(p));
    return a;
}
__device__ __forceinline__ void ldsm4(u32& r0, u32& r1, u32& r2, u32& r3, u32 addr) {
    asm volatile("ldmatrix.sync.aligned.m8n8.x4.shared.b16 {%0,%1,%2,%3}, [%4];"
        : "=r"(r0), "=r"(r1), "=r"(r2), "=r"(r3) : "r"(addr));
}
__device__ __forceinline__ void ldsm4t(u32& r0, u32& r1, u32& r2, u32& r3, u32 addr) {
    asm volatile("ldmatrix.sync.aligned.m8n8.x4.trans.shared.b16 {%0,%1,%2,%3}, [%4];"
        : "=r"(r0), "=r"(r1), "=r"(r2), "=r"(r3) : "r"(addr));
}
__device__ __forceinline__ void mma16816(float* c, const u32* a, u32 b0, u32 b1) {
    asm volatile("mma.sync.aligned.m16n8k16.row.col.f32.f16.f16.f32 "
        "{%0,%1,%2,%3}, {%4,%5,%6,%7}, {%8,%9}, {%0,%1,%2,%3};"
        : "+f"(c[0]), "+f"(c[1]), "+f"(c[2]), "+f"(c[3])
        : "r"(a[0]), "r"(a[1]), "r"(a[2]), "r"(a[3]), "r"(b0), "r"(b1));
}

// Scratch (no cudaMalloc allowed)
__device__ float  g_part[CSPLIT * MAXB * NKV * CH];   // conv partial sums (16.8MB)
__device__ __half g_kh [MAXB * NKV * CH];             // K fp16 [tok][ch]
__device__ __half g_vh [MAXB * NKV * CH];             // V fp16 [tok][ch]

// ---------------------------------------------------------------------------
// K1: spatial-reduction conv (8x8 stride 8) as K-split GEMM. CSPLIT=32:
// split = 2 consecutive positions (32KB weight slab) -> 512 blocks.
// ---------------------------------------------------------------------------
__global__ __launch_bounds__(128) void conv_kernel(
    const float* __restrict__ x, const float* __restrict__ Wsr)
{
    extern __shared__ float sW[];   // 2*64*64 floats = 32KB
    const int tid   = threadIdx.x;
    const int split = blockIdx.x & 31;
    const int tile  = blockIdx.x >> 5;

    {
        const float4* wg = (const float4*)(Wsr + (size_t)split * 8192);
        float4* sw4 = (float4*)sW;
        #pragma unroll
        for (int k = 0; k < 16; k++) sw4[k * 128 + tid] = wg[k * 128 + tid];
    }
    __syncthreads();

    const int token = tile * 128 + tid;
    const int b  = token >> 8;
    const int rm = token & 255;
    const int oh = rm >> 4;
    const int ow = rm & 15;
    const int i  = split >> 2;
    const int j0 = (split & 3) * 2;
    const float* xb = x + ((size_t)b * NQ + (size_t)(oh * 8 + i) * 128 + (ow * 8 + j0)) * CH;

    u64 acc[32];
    #pragma unroll
    for (int m = 0; m < 32; m++) acc[m] = 0ull;

    #pragma unroll
    for (int p = 0; p < 2; p++) {
        const float4*     xp = (const float4*)(xb + p * CH);
        const ulonglong2* wp = (const ulonglong2*)(sW + p * 64 * 64);
        #pragma unroll 2
        for (int c4 = 0; c4 < 16; c4++) {
            float4 xa = __ldg(xp + c4);
            #pragma unroll
            for (int e = 0; e < 4; e++) {
                float xe = (e == 0) ? xa.x : (e == 1) ? xa.y : (e == 2) ? xa.z : xa.w;
                u64 xx = pack2(xe, xe);
                const ulonglong2* wr = wp + (c4 * 4 + e) * 16;
                #pragma unroll
                for (int m = 0; m < 16; m++) {
                    ulonglong2 w = wr[m];
                    fma2(acc[2 * m + 0], xx, w.x);
                    fma2(acc[2 * m + 1], xx, w.y);
                }
            }
        }
    }

    float4* gp = (float4*)(g_part + ((size_t)split * (MAXB * NKV) + token) * CH);
    #pragma unroll
    for (int m = 0; m < 8; m++) {
        float4 r0, r1;
        unpack2(acc[4 * m + 0], r0.x, r0.y);
        unpack2(acc[4 * m + 1], r0.z, r0.w);
        unpack2(acc[4 * m + 2], r1.x, r1.y);
        unpack2(acc[4 * m + 3], r1.z, r1.w);
        gp[2 * m + 0] = r0;
        gp[2 * m + 1] = r1;
    }
}

// ---------------------------------------------------------------------------
// K2: K-split reduce + bias + LayerNorm + K/V proj -> fp16 K, V (row-major).
// ---------------------------------------------------------------------------
__global__ __launch_bounds__(256) void lnkv_kernel(
    const float* __restrict__ bsr,
    const float* __restrict__ gamma, const float* __restrict__ beta,
    const float* __restrict__ Wk, const float* __restrict__ bk,
    const float* __restrict__ Wv, const float* __restrict__ bv)
{
    __shared__ float sA[32 * 65];
    const int tid = threadIdx.x;
    const int tokbase = blockIdx.x * 32;

    for (int idx = tid; idx < 2048; idx += 256) {
        size_t off = (size_t)tokbase * CH + idx;
        float v = bsr[idx & 63];
        #pragma unroll
        for (int s = 0; s < CSPLIT; s++)
            v += g_part[(size_t)s * (MAXB * NKV * CH) + off];
        sA[(idx >> 6) * 65 + (idx & 63)] = v;
    }
    __syncthreads();

    if (tid < 32) {
        float* a = sA + tid * 65;
        float mu = 0.f;
        #pragma unroll
        for (int c = 0; c < 64; c++) mu += a[c];
        mu *= (1.0f / 64.0f);
        float var = 0.f;
        #pragma unroll
        for (int c = 0; c < 64; c++) { float d = a[c] - mu; var += d * d; }
        var *= (1.0f / 64.0f);
        float inv = rsqrtf(var + 1e-5f);
        #pragma unroll
        for (int c = 0; c < 64; c++)
            a[c] = (a[c] - mu) * inv * gamma[c] + beta[c];
    }
    __syncthreads();

    const int token = tid >> 3;
    const int c4b   = tid & 7;
    const float* ar = sA + token * 65;
    const float4* Wk4 = (const float4*)Wk;
    const float4* Wv4 = (const float4*)Wv;
    const int gtok = tokbase + token;
    #pragma unroll
    for (int of = 0; of < 2; of++) {
        int c4 = c4b + of * 8;
        float4 ka = ((const float4*)bk)[c4];
        float4 va = ((const float4*)bv)[c4];
        for (int j = 0; j < 64; j++) {
            float  av = ar[j];
            float4 wk = Wk4[j * 16 + c4];
            float4 wv = Wv4[j * 16 + c4];
            ka.x += av * wk.x; ka.y += av * wk.y; ka.z += av * wk.z; ka.w += av * wk.w;
            va.x += av * wv.x; va.y += av * wv.y; va.z += av * wv.z; va.w += av * wv.w;
        }
        __half2* kp = (__half2*)(g_kh + (size_t)gtok * CH + c4 * 4);
        kp[0] = __floats2half2_rn(ka.x, ka.y);
        kp[1] = __floats2half2_rn(ka.z, ka.w);
        __half2* vp = (__half2*)(g_vh + (size_t)gtok * CH + c4 * 4);
        vp[0] = __floats2half2_rn(va.x, va.y);
        vp[1] = __floats2half2_rn(va.z, va.w);
    }
}

// ---------------------------------------------------------------------------
// K3: raw mma.m16n8k16 fused attention, FA-style register chaining.
// CTA = 128 queries, 8 warps x 16 rows. P never touches smem.
// smem: K,V,X [stride 72 halves], Wq,Wp [stride 72]. 110592 B -> 2 CTAs/SM.
// ---------------------------------------------------------------------------
#define SM_K    0            // K  [256][72] fp16  36864B
#define SM_V    36864        // V  [256][72] fp16  36864B
#define SM_X    73728        // X  [128][72] fp16  18432B
#define SM_WQ   92160        // Wq [64][72]  fp16  9216B
#define SM_WP   101376       // Wp [64][72]  fp16  9216B
#define SM_TOTAL 110592

__global__ __launch_bounds__(256, 2) void attn_kernel(
    const float* __restrict__ x,
    const float* __restrict__ Wq, const float* __restrict__ bq,
    const float* __restrict__ Wp, const float* __restrict__ bp,
    float* __restrict__ out)
{
    extern __shared__ char smem[];
    const u32 sb = smem_u32(smem);
    const int tid = threadIdx.x;
    const int wid = tid >> 5;
    const int l   = tid & 31;
    const int wrow = wid * 16;

    const int b = blockIdx.x >> 7;
    const int qbase = blockIdx.x * 128;

    // ---- stage: X (fp32->fp16), K, V, Wq, Wp; all row stride 72 halves ----
    {
        const float4* xs = (const float4*)(x + (size_t)qbase * CH);
        #pragma unroll
        for (int it = 0; it < 8; it++) {
            int idx = tid + it * 256;         // float4 id (2048)
            int row = idx >> 4, c4 = idx & 15;
            float4 f = __ldg(xs + idx);
            __half2* d = (__half2*)(smem + SM_X + (row * 72 + c4 * 4) * 2);
            d[0] = __floats2half2_rn(f.x, f.y);
            d[1] = __floats2half2_rn(f.z, f.w);
        }
        const uint4* ks = (const uint4*)(g_kh + (size_t)b * NKV * CH);
        const uint4* vs = (const uint4*)(g_vh + (size_t)b * NKV * CH);
        #pragma unroll
        for (int it = 0; it < 8; it++) {
            int idx = tid + it * 256;         // 16B chunk (2048)
            int row = idx >> 3, sub = idx & 7;
            *(uint4*)(smem + SM_K + (row * 72 + sub * 8) * 2) = __ldg(ks + idx);
            *(uint4*)(smem + SM_V + (row * 72 + sub * 8) * 2) = __ldg(vs + idx);
        }
        #pragma unroll
        for (int it = 0; it < 8; it++) {
            int idx = tid + it * 256;         // float4 id (2048 over both W)
            int sel = idx >> 10;
            int r   = (idx >> 4) & 63, c4 = idx & 15;
            const float4* src = (const float4*)(sel ? Wp : Wq);
            float4 f = __ldg(src + (idx & 1023));
            __half2* d = (__half2*)(smem + (sel ? SM_WP : SM_WQ) + (r * 72 + c4 * 4) * 2);
            d[0] = __floats2half2_rn(f.x, f.y);
            d[1] = __floats2half2_rn(f.z, f.w);
        }
    }
    __syncthreads();

    // ldmatrix per-lane byte offsets (row stride = 144 B)
    const u32 offA  = (l & 15) * 144 + (l >> 4) * 16;                    // A row-major x4
    const u32 offBk = ((l & 7) + (l >> 4) * 8) * 144 + ((l >> 3) & 1) * 16;  // B non-trans (K)
    const u32 offBt = ((l & 7) + ((l >> 3) & 1) * 8) * 144 + (l >> 4) * 16;  // B trans (V/W)

    const u32 aK  = sb + SM_K  + offBk;
    const u32 aV  = sb + SM_V  + offBt;
    const u32 aX  = sb + SM_X  + wrow * 144 + offA;
    const u32 aWQ = sb + SM_WQ + offBt;
    const u32 aWP = sb + SM_WP + offBt;

    // ---- GEMM1: Q = (X @ Wq + bq) * 0.125, result as A-frags in regs ----
    u32 aQ[4][4];
    {
        u32 ax[4][4];
        #pragma unroll
        for (int kc = 0; kc < 4; kc++)
            ldsm4(ax[kc][0], ax[kc][1], ax[kc][2], ax[kc][3], aX + kc * 32);
        #pragma unroll
        for (int ng = 0; ng < 4; ng++) {
            float C0[4] = {0.f, 0.f, 0.f, 0.f};
            float C1[4] = {0.f, 0.f, 0.f, 0.f};
            #pragma unroll
            for (int kc = 0; kc < 4; kc++) {
                u32 b0, b1, b2, b3;
                ldsm4t(b0, b1, b2, b3, aWQ + kc * 16 * 144 + ng * 32);
                mma16816(C0, ax[kc], b0, b1);
                mma16816(C1, ax[kc], b2, b3);
            }
            int col0 = ng * 16 + (l & 3) * 2;
            float q00 = __ldg(bq + col0),     q01 = __ldg(bq + col0 + 1);
            float q10 = __ldg(bq + col0 + 8), q11 = __ldg(bq + col0 + 9);
            aQ[ng][0] = pack_h2((C0[0] + q00) * 0.125f, (C0[1] + q01) * 0.125f);
            aQ[ng][1] = pack_h2((C0[2] + q00) * 0.125f, (C0[3] + q01) * 0.125f);
            aQ[ng][2] = pack_h2((C1[0] + q10) * 0.125f, (C1[1] + q11) * 0.125f);
            aQ[ng][3] = pack_h2((C1[2] + q10) * 0.125f, (C1[3] + q11) * 0.125f);
        }
    }

    // ---- mainloop: S = exp(Q@K^T) in regs, O += P@V ----
    float O[8][4];
    #pragma unroll
    for (int m = 0; m < 8; m++)
        { O[m][0] = 0.f; O[m][1] = 0.f; O[m][2] = 0.f; O[m][3] = 0.f; }
    float ls0 = 0.f, ls1 = 0.f;

    #pragma unroll 1
    for (int c = 0; c < 16; c++) {
        const u32 kbase = aK + c * 16 * 144;
        float S0[4] = {0.f, 0.f, 0.f, 0.f};
        float S1[4] = {0.f, 0.f, 0.f, 0.f};
        #pragma unroll
        for (int kc = 0; kc < 4; kc++) {
            u32 b0, b1, b2, b3;
            ldsm4(b0, b1, b2, b3, kbase + kc * 32);
            mma16816(S0, aQ[kc], b0, b1);
            mma16816(S1, aQ[kc], b2, b3);
        }
        float e00 = __expf(S0[0]), e01 = __expf(S0[1]);
        float e02 = __expf(S0[2]), e03 = __expf(S0[3]);
        float e10 = __expf(S1[0]), e11 = __expf(S1[1]);
        float e12 = __expf(S1[2]), e13 = __expf(S1[3]);
        ls0 += (e00 + e01) + (e10 + e11);
        ls1 += (e02 + e03) + (e12 + e13);
        u32 pA[4];
        pA[0] = pack_h2(e00, e01);
        pA[1] = pack_h2(e02, e03);
        pA[2] = pack_h2(e10, e11);
        pA[3] = pack_h2(e12, e13);
        const u32 vbase = aV + c * 16 * 144;
        #pragma unroll
        for (int ng = 0; ng < 4; ng++) {
            u32 v0, v1, v2, v3;
            ldsm4t(v0, v1, v2, v3, vbase + ng * 32);
            mma16816(O[2 * ng],     pA, v0, v1);
            mma16816(O[2 * ng + 1], pA, v2, v3);
        }
    }

    ls0 += __shfl_xor_sync(0xffffffffu, ls0, 1);
    ls0 += __shfl_xor_sync(0xffffffffu, ls0, 2);
    ls1 += __shfl_xor_sync(0xffffffffu, ls1, 1);
    ls1 += __shfl_xor_sync(0xffffffffu, ls1, 2);
    const float rl0 = 1.0f / ls0;
    const float rl1 = 1.0f / ls1;

    // ---- pack O (scaled) into A-frags ----
    u32 aO[4][4];
    #pragma unroll
    for (int kc = 0; kc < 4; kc++) {
        aO[kc][0] = pack_h2(O[2 * kc][0] * rl0,     O[2 * kc][1] * rl0);
        aO[kc][1] = pack_h2(O[2 * kc][2] * rl1,     O[2 * kc][3] * rl1);
        aO[kc][2] = pack_h2(O[2 * kc + 1][0] * rl0, O[2 * kc + 1][1] * rl0);
        aO[kc][3] = pack_h2(O[2 * kc + 1][2] * rl1, O[2 * kc + 1][3] * rl1);
    }

    // ---- GEMM4: Y = O @ Wp + bp -> gmem ----
    const int row0 = qbase + wrow + (l >> 2);
    #pragma unroll
    for (int ng = 0; ng < 4; ng++) {
        float C0[4] = {0.f, 0.f, 0.f, 0.f};
        float C1[4] = {0.f, 0.f, 0.f, 0.f};
        #pragma unroll
        for (int kc = 0; kc < 4; kc++) {
            u32 b0, b1, b2, b3;
            ldsm4t(b0, b1, b2, b3, aWP + kc * 16 * 144 + ng * 32);
            mma16816(C0, aO[kc], b0, b1);
            mma16816(C1, aO[kc], b2, b3);
        }
        int col0 = ng * 16 + (l & 3) * 2;
        float p00 = __ldg(bp + col0),     p01 = __ldg(bp + col0 + 1);
        float p10 = __ldg(bp + col0 + 8), p11 = __ldg(bp + col0 + 9);
        float2* o0 = (float2*)(out + (size_t)row0 * CH + col0);
        float2* o1 = (float2*)(out + (size_t)(row0 + 8) * CH + col0);
        o0[0] = make_float2(C0[0] + p00, C0[1] + p01);
        o0[4] = make_float2(C1[0] + p10, C1[1] + p11);
        o1[0] = make_float2(C0[2] + p00, C0[3] + p01);
        o1[4] = make_float2(C1[2] + p10, C1[3] + p11);
    }
}

// ---------------------------------------------------------------------------
extern "C" void kernel_launch(void* const* d_in, const int* in_sizes, int n_in,
                              void* d_out, int out_size)
{
    const float* x     = (const float*)d_in[0];
    const float* Wq    = (const float*)d_in[1];
    const float* bq    = (const float*)d_in[2];
    const float* Wk    = (const float*)d_in[3];
    const float* bk    = (const float*)d_in[4];
    const float* Wv    = (const float*)d_in[5];
    const float* bv    = (const float*)d_in[6];
    const float* Wsr   = (const float*)d_in[7];
    const float* bsr   = (const float*)d_in[8];
    const float* gamma = (const float*)d_in[9];
    const float* beta  = (const float*)d_in[10];
    const float* Wp    = (const float*)d_in[11];
    const float* bp    = (const float*)d_in[12];
    float* out = (float*)d_out;

    int B = in_sizes[0] / (NQ * CH);
    if (B > MAXB) B = MAXB;

    const int conv_smem = 2 * 64 * 64 * 4;        // 32768 B
    cudaFuncSetAttribute(conv_kernel, cudaFuncAttributeMaxDynamicSharedMemorySize, conv_smem);
    cudaFuncSetAttribute(attn_kernel, cudaFuncAttributeMaxDynamicSharedMemorySize, SM_TOTAL);

    conv_kernel<<<B * 2 * CSPLIT, 128, conv_smem>>>(x, Wsr);
    lnkv_kernel<<<B * 8, 256>>>(bsr, gamma, beta, Wk, bk, Wv, bv);
    attn_kernel<<<B * 128, 256, SM_TOTAL>>>(x, Wq, bq, Wp, bp, out);
}

// round 8
// speedup vs baseline: 6.7349x; 1.2700x over previous
#include <cuda_runtime.h>
#include <cuda_fp16.h>

#define NQ   16384
#define NKV  256
#define CH   64
#define MAXB 8
#define CVSPLIT 8

typedef unsigned long long u64;
typedef unsigned int u32;

__device__ __forceinline__ u32 pack_h2(float lo, float hi) {
    u32 r; asm("cvt.rn.f16x2.f32 %0, %1, %2;" : "=r"(r) : "f"(hi), "f"(lo)); return r;
}
__device__ __forceinline__ u32 smem_u32(const void* p) {
    u32 a; asm("{ .reg .u64 t; cvta.to.shared.u64 t, %1; cvt.u32.u64 %0, t; }" : "=r"(a) : "l"(p));
    return a;
}
__device__ __forceinline__ void ldsm4(u32& r0, u32& r1, u32& r2, u32& r3, u32 addr) {
    asm volatile("ldmatrix.sync.aligned.m8n8.x4.shared.b16 {%0,%1,%2,%3}, [%4];"
        : "=r"(r0), "=r"(r1), "=r"(r2), "=r"(r3) : "r"(addr));
}
__device__ __forceinline__ void ldsm4t(u32& r0, u32& r1, u32& r2, u32& r3, u32 addr) {
    asm volatile("ldmatrix.sync.aligned.m8n8.x4.trans.shared.b16 {%0,%1,%2,%3}, [%4];"
        : "=r"(r0), "=r"(r1), "=r"(r2), "=r"(r3) : "r"(addr));
}
__device__ __forceinline__ void mma16816(float* c, const u32* a, u32 b0, u32 b1) {
    asm volatile("mma.sync.aligned.m16n8k16.row.col.f32.f16.f16.f32 "
        "{%0,%1,%2,%3}, {%4,%5,%6,%7}, {%8,%9}, {%0,%1,%2,%3};"
        : "+f"(c[0]), "+f"(c[1]), "+f"(c[2]), "+f"(c[3])
        : "r"(a[0]), "r"(a[1]), "r"(a[2]), "r"(a[3]), "r"(b0), "r"(b1));
}
__device__ __forceinline__ u32 ex2_h2(u32 s) {
    u32 d; asm("ex2.approx.f16x2 %0, %1;" : "=r"(d) : "r"(s)); return d;
}

// Scratch (no cudaMalloc allowed)
__device__ float  g_part[CVSPLIT * MAXB * NKV * CH];  // conv partials (4MB)
__device__ __half g_kh [MAXB * NKV * CH];             // K fp16 [tok][ch]
__device__ __half g_vh [MAXB * NKV * CH];             // V fp16 [tok][ch]

// ---------------------------------------------------------------------------
// K1: conv (8x8 stride 8) via mma.m16n8k16 with split-fp16 (hi/lo, 3 terms).
// Block = 64 tokens (b, 4 oh rows x 16 ow) x split i (kernel row).
// Loop j=0..7: stage A(64x64) and W(64x64) as hi/lo fp16, 3-term mma.
// ---------------------------------------------------------------------------
#define CV_AHI 0
#define CV_ALO 9216
#define CV_WHI 18432
#define CV_WLO 27648
#define CV_SMEM 36864

__global__ __launch_bounds__(128) void conv_kernel(
    const float* __restrict__ x, const float* __restrict__ Wsr)
{
    extern __shared__ char smc[];
    const u32 sb = smem_u32(smc);
    const int tid = threadIdx.x;
    const int wid = tid >> 5;
    const int l   = tid & 31;
    const int wrow = wid * 16;

    const int split = blockIdx.x & 7;       // kernel row i
    const int tile  = blockIdx.x >> 3;      // 0..4B-1
    const int b     = tile >> 2;
    const int oht   = tile & 3;
    const int i     = split;

    const u32 offA  = (l & 15) * 144 + (l >> 4) * 16;
    const u32 offBt = ((l & 7) + ((l >> 3) & 1) * 8) * 144 + (l >> 4) * 16;

    float C[4][2][4];
    #pragma unroll
    for (int ng = 0; ng < 4; ng++)
        #pragma unroll
        for (int h = 0; h < 2; h++)
            { C[ng][h][0] = 0.f; C[ng][h][1] = 0.f; C[ng][h][2] = 0.f; C[ng][h][3] = 0.f; }

    const int stok = tid >> 1;          // staging token 0..63
    const int part = tid & 1;           // column half
    const int sohl = stok >> 4, sow = stok & 15;

    #pragma unroll 1
    for (int j = 0; j < 8; j++) {
        __syncthreads();
        // ---- stage A: x rows for this (i, j), 64 tokens x 64 ch ----
        {
            const float4* src = (const float4*)(x +
                ((size_t)(b * 128 + (oht * 4 + sohl) * 8 + i) * 128 + sow * 8 + j) * CH
                + part * 32);
            #pragma unroll
            for (int e = 0; e < 8; e++) {
                float4 f = __ldg(src + e);
                __half2 h01 = __floats2half2_rn(f.x, f.y);
                __half2 h23 = __floats2half2_rn(f.z, f.w);
                float2 b01 = __half22float2(h01);
                float2 b23 = __half22float2(h23);
                __half2 l01 = __floats2half2_rn(f.x - b01.x, f.y - b01.y);
                __half2 l23 = __floats2half2_rn(f.z - b23.x, f.w - b23.y);
                int o = (stok * 72 + part * 32 + e * 4) * 2;
                *(__half2*)(smc + CV_AHI + o)     = h01;
                *(__half2*)(smc + CV_AHI + o + 4) = h23;
                *(__half2*)(smc + CV_ALO + o)     = l01;
                *(__half2*)(smc + CV_ALO + o + 4) = l23;
            }
        }
        // ---- stage W row j: 64 ci x 64 co ----
        {
            const float4* src = (const float4*)(Wsr +
                ((size_t)((i * 8 + j) * 64 + stok)) * 64 + part * 32);
            #pragma unroll
            for (int e = 0; e < 8; e++) {
                float4 f = __ldg(src + e);
                __half2 h01 = __floats2half2_rn(f.x, f.y);
                __half2 h23 = __floats2half2_rn(f.z, f.w);
                float2 b01 = __half22float2(h01);
                float2 b23 = __half22float2(h23);
                __half2 l01 = __floats2half2_rn(f.x - b01.x, f.y - b01.y);
                __half2 l23 = __floats2half2_rn(f.z - b23.x, f.w - b23.y);
                int o = (stok * 72 + part * 32 + e * 4) * 2;
                *(__half2*)(smc + CV_WHI + o)     = h01;
                *(__half2*)(smc + CV_WHI + o + 4) = h23;
                *(__half2*)(smc + CV_WLO + o)     = l01;
                *(__half2*)(smc + CV_WLO + o + 4) = l23;
            }
        }
        __syncthreads();

        // ---- 3-term mma ----
        u32 axh[4][4], axl[4][4];
        #pragma unroll
        for (int kc = 0; kc < 4; kc++) {
            ldsm4(axh[kc][0], axh[kc][1], axh[kc][2], axh[kc][3],
                  sb + CV_AHI + wrow * 144 + offA + kc * 32);
            ldsm4(axl[kc][0], axl[kc][1], axl[kc][2], axl[kc][3],
                  sb + CV_ALO + wrow * 144 + offA + kc * 32);
        }
        #pragma unroll
        for (int ng = 0; ng < 4; ng++) {
            #pragma unroll
            for (int kc = 0; kc < 4; kc++) {
                u32 h0, h1, h2, h3, q0, q1, q2, q3;
                ldsm4t(h0, h1, h2, h3, sb + CV_WHI + offBt + kc * 16 * 144 + ng * 32);
                ldsm4t(q0, q1, q2, q3, sb + CV_WLO + offBt + kc * 16 * 144 + ng * 32);
                mma16816(C[ng][0], axh[kc], h0, h1);
                mma16816(C[ng][1], axh[kc], h2, h3);
                mma16816(C[ng][0], axl[kc], h0, h1);
                mma16816(C[ng][1], axl[kc], h2, h3);
                mma16816(C[ng][0], axh[kc], q0, q1);
                mma16816(C[ng][1], axh[kc], q2, q3);
            }
        }
    }

    // ---- epilogue: partials to g_part[split][token][co] ----
    {
        int tl0 = wrow + (l >> 2);
        int tl1 = tl0 + 8;
        int gt0 = b * 256 + (oht * 4 + (tl0 >> 4)) * 16 + (tl0 & 15);
        int gt1 = b * 256 + (oht * 4 + (tl1 >> 4)) * 16 + (tl1 & 15);
        float* gp = g_part + (size_t)split * (MAXB * NKV * CH);
        #pragma unroll
        for (int ng = 0; ng < 4; ng++) {
            int col0 = ng * 16 + (l & 3) * 2;
            *(float2*)(gp + (size_t)gt0 * CH + col0)     = make_float2(C[ng][0][0], C[ng][0][1]);
            *(float2*)(gp + (size_t)gt0 * CH + col0 + 8) = make_float2(C[ng][1][0], C[ng][1][1]);
            *(float2*)(gp + (size_t)gt1 * CH + col0)     = make_float2(C[ng][0][2], C[ng][0][3]);
            *(float2*)(gp + (size_t)gt1 * CH + col0 + 8) = make_float2(C[ng][1][2], C[ng][1][3]);
        }
    }
}

// ---------------------------------------------------------------------------
// K2: K-split reduce + bias + LayerNorm + K/V proj -> fp16 K, V (row-major).
// ---------------------------------------------------------------------------
__global__ __launch_bounds__(256) void lnkv_kernel(
    const float* __restrict__ bsr,
    const float* __restrict__ gamma, const float* __restrict__ beta,
    const float* __restrict__ Wk, const float* __restrict__ bk,
    const float* __restrict__ Wv, const float* __restrict__ bv)
{
    __shared__ float sA[32 * 65];
    const int tid = threadIdx.x;
    const int tokbase = blockIdx.x * 32;

    for (int idx = tid; idx < 2048; idx += 256) {
        size_t off = (size_t)tokbase * CH + idx;
        float v = bsr[idx & 63];
        #pragma unroll
        for (int s = 0; s < CVSPLIT; s++)
            v += g_part[(size_t)s * (MAXB * NKV * CH) + off];
        sA[(idx >> 6) * 65 + (idx & 63)] = v;
    }
    __syncthreads();

    if (tid < 32) {
        float* a = sA + tid * 65;
        float mu = 0.f;
        #pragma unroll
        for (int c = 0; c < 64; c++) mu += a[c];
        mu *= (1.0f / 64.0f);
        float var = 0.f;
        #pragma unroll
        for (int c = 0; c < 64; c++) { float d = a[c] - mu; var += d * d; }
        var *= (1.0f / 64.0f);
        float inv = rsqrtf(var + 1e-5f);
        #pragma unroll
        for (int c = 0; c < 64; c++)
            a[c] = (a[c] - mu) * inv * gamma[c] + beta[c];
    }
    __syncthreads();

    const int token = tid >> 3;
    const int c4b   = tid & 7;
    const float* ar = sA + token * 65;
    const float4* Wk4 = (const float4*)Wk;
    const float4* Wv4 = (const float4*)Wv;
    const int gtok = tokbase + token;
    #pragma unroll
    for (int of = 0; of < 2; of++) {
        int c4 = c4b + of * 8;
        float4 ka = ((const float4*)bk)[c4];
        float4 va = ((const float4*)bv)[c4];
        for (int j = 0; j < 64; j++) {
            float  av = ar[j];
            float4 wk = Wk4[j * 16 + c4];
            float4 wv = Wv4[j * 16 + c4];
            ka.x += av * wk.x; ka.y += av * wk.y; ka.z += av * wk.z; ka.w += av * wk.w;
            va.x += av * wv.x; va.y += av * wv.y; va.z += av * wv.z; va.w += av * wv.w;
        }
        __half2* kp = (__half2*)(g_kh + (size_t)gtok * CH + c4 * 4);
        kp[0] = __floats2half2_rn(ka.x, ka.y);
        kp[1] = __floats2half2_rn(ka.z, ka.w);
        __half2* vp = (__half2*)(g_vh + (size_t)gtok * CH + c4 * 4);
        vp[0] = __floats2half2_rn(va.x, va.y);
        vp[1] = __floats2half2_rn(va.z, va.w);
    }
}

// ---------------------------------------------------------------------------
// K3: raw mma.m16n8k16 fused attention, FA-style register chaining.
// q pre-scaled by 0.125*log2(e); softmax via ex2.approx.f16x2.
// ---------------------------------------------------------------------------
#define SM_K    0            // K  [256][72] fp16  36864B
#define SM_V    36864        // V  [256][72] fp16  36864B
#define SM_X    73728        // X  [128][72] fp16  18432B
#define SM_WQ   92160        // Wq [64][72]  fp16  9216B
#define SM_WP   101376       // Wp [64][72]  fp16  9216B
#define SM_TOTAL 110592

#define QSCALE 0.1803368801f   // 0.125 * log2(e)

__global__ __launch_bounds__(256, 2) void attn_kernel(
    const float* __restrict__ x,
    const float* __restrict__ Wq, const float* __restrict__ bq,
    const float* __restrict__ Wp, const float* __restrict__ bp,
    float* __restrict__ out)
{
    extern __shared__ char smem[];
    const u32 sb = smem_u32(smem);
    const int tid = threadIdx.x;
    const int wid = tid >> 5;
    const int l   = tid & 31;
    const int wrow = wid * 16;

    const int b = blockIdx.x >> 7;
    const int qbase = blockIdx.x * 128;

    // ---- stage: X (fp32->fp16), K, V, Wq, Wp; all row stride 72 halves ----
    {
        const float4* xs = (const float4*)(x + (size_t)qbase * CH);
        #pragma unroll
        for (int it = 0; it < 8; it++) {
            int idx = tid + it * 256;
            int row = idx >> 4, c4 = idx & 15;
            float4 f = __ldg(xs + idx);
            __half2* d = (__half2*)(smem + SM_X + (row * 72 + c4 * 4) * 2);
            d[0] = __floats2half2_rn(f.x, f.y);
            d[1] = __floats2half2_rn(f.z, f.w);
        }
        const uint4* ks = (const uint4*)(g_kh + (size_t)b * NKV * CH);
        const uint4* vs = (const uint4*)(g_vh + (size_t)b * NKV * CH);
        #pragma unroll
        for (int it = 0; it < 8; it++) {
            int idx = tid + it * 256;
            int row = idx >> 3, sub = idx & 7;
            *(uint4*)(smem + SM_K + (row * 72 + sub * 8) * 2) = __ldg(ks + idx);
            *(uint4*)(smem + SM_V + (row * 72 + sub * 8) * 2) = __ldg(vs + idx);
        }
        #pragma unroll
        for (int it = 0; it < 8; it++) {
            int idx = tid + it * 256;
            int sel = idx >> 10;
            int r   = (idx >> 4) & 63, c4 = idx & 15;
            const float4* src = (const float4*)(sel ? Wp : Wq);
            float4 f = __ldg(src + (idx & 1023));
            __half2* d = (__half2*)(smem + (sel ? SM_WP : SM_WQ) + (r * 72 + c4 * 4) * 2);
            d[0] = __floats2half2_rn(f.x, f.y);
            d[1] = __floats2half2_rn(f.z, f.w);
        }
    }
    __syncthreads();

    const u32 offA  = (l & 15) * 144 + (l >> 4) * 16;
    const u32 offBk = ((l & 7) + (l >> 4) * 8) * 144 + ((l >> 3) & 1) * 16;
    const u32 offBt = ((l & 7) + ((l >> 3) & 1) * 8) * 144 + (l >> 4) * 16;

    const u32 aK  = sb + SM_K  + offBk;
    const u32 aV  = sb + SM_V  + offBt;
    const u32 aX  = sb + SM_X  + wrow * 144 + offA;
    const u32 aWQ = sb + SM_WQ + offBt;
    const u32 aWP = sb + SM_WP + offBt;

    // ---- GEMM1: Q = (X @ Wq + bq) * QSCALE, A-frags in regs ----
    u32 aQ[4][4];
    {
        u32 ax[4][4];
        #pragma unroll
        for (int kc = 0; kc < 4; kc++)
            ldsm4(ax[kc][0], ax[kc][1], ax[kc][2], ax[kc][3], aX + kc * 32);
        #pragma unroll
        for (int ng = 0; ng < 4; ng++) {
            float C0[4] = {0.f, 0.f, 0.f, 0.f};
            float C1[4] = {0.f, 0.f, 0.f, 0.f};
            #pragma unroll
            for (int kc = 0; kc < 4; kc++) {
                u32 b0, b1, b2, b3;
                ldsm4t(b0, b1, b2, b3, aWQ + kc * 16 * 144 + ng * 32);
                mma16816(C0, ax[kc], b0, b1);
                mma16816(C1, ax[kc], b2, b3);
            }
            int col0 = ng * 16 + (l & 3) * 2;
            float q00 = __ldg(bq + col0),     q01 = __ldg(bq + col0 + 1);
            float q10 = __ldg(bq + col0 + 8), q11 = __ldg(bq + col0 + 9);
            aQ[ng][0] = pack_h2((C0[0] + q00) * QSCALE, (C0[1] + q01) * QSCALE);
            aQ[ng][1] = pack_h2((C0[2] + q00) * QSCALE, (C0[3] + q01) * QSCALE);
            aQ[ng][2] = pack_h2((C1[0] + q10) * QSCALE, (C1[1] + q11) * QSCALE);
            aQ[ng][3] = pack_h2((C1[2] + q10) * QSCALE, (C1[3] + q11) * QSCALE);
        }
    }

    // ---- mainloop: P = 2^(Q@K^T) via ex2.f16x2, O += P@V ----
    float O[8][4];
    #pragma unroll
    for (int m = 0; m < 8; m++)
        { O[m][0] = 0.f; O[m][1] = 0.f; O[m][2] = 0.f; O[m][3] = 0.f; }
    float ls0 = 0.f, ls1 = 0.f;

    #pragma unroll 1
    for (int c = 0; c < 16; c++) {
        const u32 kbase = aK + c * 16 * 144;
        float S0[4] = {0.f, 0.f, 0.f, 0.f};
        float S1[4] = {0.f, 0.f, 0.f, 0.f};
        #pragma unroll
        for (int kc = 0; kc < 4; kc++) {
            u32 b0, b1, b2, b3;
            ldsm4(b0, b1, b2, b3, kbase + kc * 32);
            mma16816(S0, aQ[kc], b0, b1);
            mma16816(S1, aQ[kc], b2, b3);
        }
        u32 pA[4];
        pA[0] = ex2_h2(pack_h2(S0[0], S0[1]));
        pA[1] = ex2_h2(pack_h2(S0[2], S0[3]));
        pA[2] = ex2_h2(pack_h2(S1[0], S1[1]));
        pA[3] = ex2_h2(pack_h2(S1[2], S1[3]));
        {
            __half2 s02 = __hadd2(*(__half2*)&pA[0], *(__half2*)&pA[2]);
            __half2 s13 = __hadd2(*(__half2*)&pA[1], *(__half2*)&pA[3]);
            float2 f0 = __half22float2(s02);
            float2 f1 = __half22float2(s13);
            ls0 += f0.x + f0.y;
            ls1 += f1.x + f1.y;
        }
        const u32 vbase = aV + c * 16 * 144;
        #pragma unroll
        for (int ng = 0; ng < 4; ng++) {
            u32 v0, v1, v2, v3;
            ldsm4t(v0, v1, v2, v3, vbase + ng * 32);
            mma16816(O[2 * ng],     pA, v0, v1);
            mma16816(O[2 * ng + 1], pA, v2, v3);
        }
    }

    ls0 += __shfl_xor_sync(0xffffffffu, ls0, 1);
    ls0 += __shfl_xor_sync(0xffffffffu, ls0, 2);
    ls1 += __shfl_xor_sync(0xffffffffu, ls1, 1);
    ls1 += __shfl_xor_sync(0xffffffffu, ls1, 2);
    const float rl0 = 1.0f / ls0;
    const float rl1 = 1.0f / ls1;

    // ---- pack O (scaled) into A-frags ----
    u32 aO[4][4];
    #pragma unroll
    for (int kc = 0; kc < 4; kc++) {
        aO[kc][0] = pack_h2(O[2 * kc][0] * rl0,     O[2 * kc][1] * rl0);
        aO[kc][1] = pack_h2(O[2 * kc][2] * rl1,     O[2 * kc][3] * rl1);
        aO[kc][2] = pack_h2(O[2 * kc + 1][0] * rl0, O[2 * kc + 1][1] * rl0);
        aO[kc][3] = pack_h2(O[2 * kc + 1][2] * rl1, O[2 * kc + 1][3] * rl1);
    }

    // ---- GEMM4: Y = O @ Wp + bp -> gmem ----
    const int row0 = qbase + wrow + (l >> 2);
    #pragma unroll
    for (int ng = 0; ng < 4; ng++) {
        float C0[4] = {0.f, 0.f, 0.f, 0.f};
        float C1[4] = {0.f, 0.f, 0.f, 0.f};
        #pragma unroll
        for (int kc = 0; kc < 4; kc++) {
            u32 b0, b1, b2, b3;
            ldsm4t(b0, b1, b2, b3, aWP + kc * 16 * 144 + ng * 32);
            mma16816(C0, aO[kc], b0, b1);
            mma16816(C1, aO[kc], b2, b3);
        }
        int col0 = ng * 16 + (l & 3) * 2;
        float p00 = __ldg(bp + col0),     p01 = __ldg(bp + col0 + 1);
        float p10 = __ldg(bp + col0 + 8), p11 = __ldg(bp + col0 + 9);
        float2* o0 = (float2*)(out + (size_t)row0 * CH + col0);
        float2* o1 = (float2*)(out + (size_t)(row0 + 8) * CH + col0);
        o0[0] = make_float2(C0[0] + p00, C0[1] + p01);
        o0[4] = make_float2(C1[0] + p10, C1[1] + p11);
        o1[0] = make_float2(C0[2] + p00, C0[3] + p01);
        o1[4] = make_float2(C1[2] + p10, C1[3] + p11);
    }
}

// ---------------------------------------------------------------------------
extern "C" void kernel_launch(void* const* d_in, const int* in_sizes, int n_in,
                              void* d_out, int out_size)
{
    const float* x     = (const float*)d_in[0];
    const float* Wq    = (const float*)d_in[1];
    const float* bq    = (const float*)d_in[2];
    const float* Wk    = (const float*)d_in[3];
    const float* bk    = (const float*)d_in[4];
    const float* Wv    = (const float*)d_in[5];
    const float* bv    = (const float*)d_in[6];
    const float* Wsr   = (const float*)d_in[7];
    const float* bsr   = (const float*)d_in[8];
    const float* gamma = (const float*)d_in[9];
    const float* beta  = (const float*)d_in[10];
    const float* Wp    = (const float*)d_in[11];
    const float* bp    = (const float*)d_in[12];
    float* out = (float*)d_out;

    int B = in_sizes[0] / (NQ * CH);
    if (B > MAXB) B = MAXB;

    cudaFuncSetAttribute(attn_kernel, cudaFuncAttributeMaxDynamicSharedMemorySize, SM_TOTAL);

    conv_kernel<<<B * 4 * CVSPLIT, 128, CV_SMEM>>>(x, Wsr);
    lnkv_kernel<<<B * 8, 256>>>(bsr, gamma, beta, Wk, bk, Wv, bv);
    attn_kernel<<<B * 128, 256, SM_TOTAL>>>(x, Wq, bq, Wp, bp, out);
}

// round 9
// speedup vs baseline: 7.4383x; 1.1044x over previous
#include <cuda_runtime.h>
#include <cuda_fp16.h>

#define NQ   16384
#define NKV  256
#define CH   64
#define MAXB 8
#define CVSPLIT 8

typedef unsigned long long u64;
typedef unsigned int u32;

__device__ __forceinline__ u32 pack_h2(float lo, float hi) {
    u32 r; asm("cvt.rn.f16x2.f32 %0, %1, %2;" : "=r"(r) : "f"(hi), "f"(lo)); return r;
}
__device__ __forceinline__ u32 smem_u32(const void* p) {
    u32 a; asm("{ .reg .u64 t; cvta.to.shared.u64 t, %1; cvt.u32.u64 %0, t; }" : "=r"(a) : "l"(p));
    return a;
}
__device__ __forceinline__ void ldsm4(u32& r0, u32& r1, u32& r2, u32& r3, u32 addr) {
    asm volatile("ldmatrix.sync.aligned.m8n8.x4.shared.b16 {%0,%1,%2,%3}, [%4];"
        : "=r"(r0), "=r"(r1), "=r"(r2), "=r"(r3) : "r"(addr));
}
__device__ __forceinline__ void ldsm4t(u32& r0, u32& r1, u32& r2, u32& r3, u32 addr) {
    asm volatile("ldmatrix.sync.aligned.m8n8.x4.trans.shared.b16 {%0,%1,%2,%3}, [%4];"
        : "=r"(r0), "=r"(r1), "=r"(r2), "=r"(r3) : "r"(addr));
}
__device__ __forceinline__ void mma16816(float* c, const u32* a, u32 b0, u32 b1) {
    asm volatile("mma.sync.aligned.m16n8k16.row.col.f32.f16.f16.f32 "
        "{%0,%1,%2,%3}, {%4,%5,%6,%7}, {%8,%9}, {%0,%1,%2,%3};"
        : "+f"(c[0]), "+f"(c[1]), "+f"(c[2]), "+f"(c[3])
        : "r"(a[0]), "r"(a[1]), "r"(a[2]), "r"(a[3]), "r"(b0), "r"(b1));
}
__device__ __forceinline__ u32 ex2_h2(u32 s) {
    u32 d; asm("ex2.approx.f16x2 %0, %1;" : "=r"(d) : "r"(s)); return d;
}

// Scratch (no cudaMalloc allowed)
__device__ float  g_part[CVSPLIT * MAXB * NKV * CH];  // conv partials (4MB)
__device__ __half g_kh [MAXB * NKV * CH];             // K fp16 [tok][ch]
__device__ __half g_vh [MAXB * NKV * CH];             // V fp16 [tok][ch]

// ---------------------------------------------------------------------------
// K1: conv (8x8 stride 8) via mma.m16n8k16 split-fp16 (hi/lo, 3 terms).
// 256 threads; block = 64 tokens x split i. 8 warp-tiles = 4 rowtiles x 2 co.
// ---------------------------------------------------------------------------
#define CV_AHI 0
#define CV_ALO 9216
#define CV_WHI 18432
#define CV_WLO 27648
#define CV_SMEM 36864

__global__ __launch_bounds__(256) void conv_kernel(
    const float* __restrict__ x, const float* __restrict__ Wsr)
{
    extern __shared__ char smc[];
    const u32 sb = smem_u32(smc);
    const int tid = threadIdx.x;
    const int wid = tid >> 5;
    const int l   = tid & 31;
    const int rt  = wid >> 1;         // rowtile 0..3
    const int coh = wid & 1;          // co half
    const int wrow = rt * 16;

    const int split = blockIdx.x & 7;       // kernel row i
    const int tile  = blockIdx.x >> 3;
    const int b     = tile >> 2;
    const int oht   = tile & 3;
    const int i     = split;

    const u32 offA  = (l & 15) * 144 + (l >> 4) * 16;
    const u32 offBt = ((l & 7) + ((l >> 3) & 1) * 8) * 144 + (l >> 4) * 16;

    float C[2][2][4];
    #pragma unroll
    for (int ng = 0; ng < 2; ng++)
        #pragma unroll
        for (int h = 0; h < 2; h++)
            { C[ng][h][0] = 0.f; C[ng][h][1] = 0.f; C[ng][h][2] = 0.f; C[ng][h][3] = 0.f; }

    const int stok = tid >> 2;          // staging token/row 0..63
    const int qq   = tid & 3;           // 16-ch quarter
    const int sohl = stok >> 4, sow = stok & 15;

    #pragma unroll 1
    for (int j = 0; j < 8; j++) {
        __syncthreads();
        // ---- stage A: 64 tokens x 64 ch for this (i,j) ----
        {
            const float4* src = (const float4*)(x +
                ((size_t)(b * 128 + (oht * 4 + sohl) * 8 + i) * 128 + sow * 8 + j) * CH
                + qq * 16);
            #pragma unroll
            for (int e = 0; e < 4; e++) {
                float4 f = __ldg(src + e);
                __half2 h01 = __floats2half2_rn(f.x, f.y);
                __half2 h23 = __floats2half2_rn(f.z, f.w);
                float2 b01 = __half22float2(h01);
                float2 b23 = __half22float2(h23);
                __half2 l01 = __floats2half2_rn(f.x - b01.x, f.y - b01.y);
                __half2 l23 = __floats2half2_rn(f.z - b23.x, f.w - b23.y);
                int o = (stok * 72 + qq * 16 + e * 4) * 2;
                *(__half2*)(smc + CV_AHI + o)     = h01;
                *(__half2*)(smc + CV_AHI + o + 4) = h23;
                *(__half2*)(smc + CV_ALO + o)     = l01;
                *(__half2*)(smc + CV_ALO + o + 4) = l23;
            }
        }
        // ---- stage W row j: 64 ci x 64 co ----
        {
            const float4* src = (const float4*)(Wsr +
                ((size_t)((i * 8 + j) * 64 + stok)) * 64 + qq * 16);
            #pragma unroll
            for (int e = 0; e < 4; e++) {
                float4 f = __ldg(src + e);
                __half2 h01 = __floats2half2_rn(f.x, f.y);
                __half2 h23 = __floats2half2_rn(f.z, f.w);
                float2 b01 = __half22float2(h01);
                float2 b23 = __half22float2(h23);
                __half2 l01 = __floats2half2_rn(f.x - b01.x, f.y - b01.y);
                __half2 l23 = __floats2half2_rn(f.z - b23.x, f.w - b23.y);
                int o = (stok * 72 + qq * 16 + e * 4) * 2;
                *(__half2*)(smc + CV_WHI + o)     = h01;
                *(__half2*)(smc + CV_WHI + o + 4) = h23;
                *(__half2*)(smc + CV_WLO + o)     = l01;
                *(__half2*)(smc + CV_WLO + o + 4) = l23;
            }
        }
        __syncthreads();

        // ---- 3-term mma (16 rows x 32 co per warp) ----
        u32 axh[4][4], axl[4][4];
        #pragma unroll
        for (int kc = 0; kc < 4; kc++) {
            ldsm4(axh[kc][0], axh[kc][1], axh[kc][2], axh[kc][3],
                  sb + CV_AHI + wrow * 144 + offA + kc * 32);
            ldsm4(axl[kc][0], axl[kc][1], axl[kc][2], axl[kc][3],
                  sb + CV_ALO + wrow * 144 + offA + kc * 32);
        }
        #pragma unroll
        for (int ng = 0; ng < 2; ng++) {
            const int ngg = coh * 2 + ng;
            #pragma unroll
            for (int kc = 0; kc < 4; kc++) {
                u32 h0, h1, h2, h3, q0, q1, q2, q3;
                ldsm4t(h0, h1, h2, h3, sb + CV_WHI + offBt + kc * 16 * 144 + ngg * 32);
                ldsm4t(q0, q1, q2, q3, sb + CV_WLO + offBt + kc * 16 * 144 + ngg * 32);
                mma16816(C[ng][0], axh[kc], h0, h1);
                mma16816(C[ng][1], axh[kc], h2, h3);
                mma16816(C[ng][0], axl[kc], h0, h1);
                mma16816(C[ng][1], axl[kc], h2, h3);
                mma16816(C[ng][0], axh[kc], q0, q1);
                mma16816(C[ng][1], axh[kc], q2, q3);
            }
        }
    }

    // ---- epilogue: partials to g_part[split][token][co] ----
    {
        int tl0 = wrow + (l >> 2);
        int tl1 = tl0 + 8;
        int gt0 = b * 256 + (oht * 4 + (tl0 >> 4)) * 16 + (tl0 & 15);
        int gt1 = b * 256 + (oht * 4 + (tl1 >> 4)) * 16 + (tl1 & 15);
        float* gp = g_part + (size_t)split * (MAXB * NKV * CH);
        #pragma unroll
        for (int ng = 0; ng < 2; ng++) {
            int col0 = (coh * 2 + ng) * 16 + (l & 3) * 2;
            *(float2*)(gp + (size_t)gt0 * CH + col0)     = make_float2(C[ng][0][0], C[ng][0][1]);
            *(float2*)(gp + (size_t)gt0 * CH + col0 + 8) = make_float2(C[ng][1][0], C[ng][1][1]);
            *(float2*)(gp + (size_t)gt1 * CH + col0)     = make_float2(C[ng][0][2], C[ng][0][3]);
            *(float2*)(gp + (size_t)gt1 * CH + col0 + 8) = make_float2(C[ng][1][2], C[ng][1][3]);
        }
    }
}

// ---------------------------------------------------------------------------
// K2: K-split reduce + bias + LayerNorm + K/V proj -> fp16 K, V (row-major).
// ---------------------------------------------------------------------------
__global__ __launch_bounds__(256) void lnkv_kernel(
    const float* __restrict__ bsr,
    const float* __restrict__ gamma, const float* __restrict__ beta,
    const float* __restrict__ Wk, const float* __restrict__ bk,
    const float* __restrict__ Wv, const float* __restrict__ bv)
{
    __shared__ float sA[32 * 65];
    const int tid = threadIdx.x;
    const int tokbase = blockIdx.x * 32;

    for (int idx = tid; idx < 2048; idx += 256) {
        size_t off = (size_t)tokbase * CH + idx;
        float v = bsr[idx & 63];
        #pragma unroll
        for (int s = 0; s < CVSPLIT; s++)
            v += g_part[(size_t)s * (MAXB * NKV * CH) + off];
        sA[(idx >> 6) * 65 + (idx & 63)] = v;
    }
    __syncthreads();

    if (tid < 32) {
        float* a = sA + tid * 65;
        float mu = 0.f;
        #pragma unroll
        for (int c = 0; c < 64; c++) mu += a[c];
        mu *= (1.0f / 64.0f);
        float var = 0.f;
        #pragma unroll
        for (int c = 0; c < 64; c++) { float d = a[c] - mu; var += d * d; }
        var *= (1.0f / 64.0f);
        float inv = rsqrtf(var + 1e-5f);
        #pragma unroll
        for (int c = 0; c < 64; c++)
            a[c] = (a[c] - mu) * inv * gamma[c] + beta[c];
    }
    __syncthreads();

    const int token = tid >> 3;
    const int c4b   = tid & 7;
    const float* ar = sA + token * 65;
    const float4* Wk4 = (const float4*)Wk;
    const float4* Wv4 = (const float4*)Wv;
    const int gtok = tokbase + token;
    #pragma unroll
    for (int of = 0; of < 2; of++) {
        int c4 = c4b + of * 8;
        float4 ka = ((const float4*)bk)[c4];
        float4 va = ((const float4*)bv)[c4];
        for (int j = 0; j < 64; j++) {
            float  av = ar[j];
            float4 wk = Wk4[j * 16 + c4];
            float4 wv = Wv4[j * 16 + c4];
            ka.x += av * wk.x; ka.y += av * wk.y; ka.z += av * wk.z; ka.w += av * wk.w;
            va.x += av * wv.x; va.y += av * wv.y; va.z += av * wv.z; va.w += av * wv.w;
        }
        __half2* kp = (__half2*)(g_kh + (size_t)gtok * CH + c4 * 4);
        kp[0] = __floats2half2_rn(ka.x, ka.y);
        kp[1] = __floats2half2_rn(ka.z, ka.w);
        __half2* vp = (__half2*)(g_vh + (size_t)gtok * CH + c4 * 4);
        vp[0] = __floats2half2_rn(va.x, va.y);
        vp[1] = __floats2half2_rn(va.z, va.w);
    }
}

// ---------------------------------------------------------------------------
// K3: mma fused attention; CTA = 256 queries, 8 warps x 32 rows (2 rowgroups).
// K-frags loaded once per kv-chunk and shared across rowgroups.
// ---------------------------------------------------------------------------
#define SM_K    0            // K  [256][72] fp16  36864B
#define SM_V    36864        // V  [256][72] fp16  36864B
#define SM_X    73728        // X  [256][72] fp16  36864B
#define SM_WQ   110592       // Wq [64][72]  fp16  9216B
#define SM_WP   119808       // Wp [64][72]  fp16  9216B
#define SM_TOTAL 129024

#define QSCALE 0.1803368801f   // 0.125 * log2(e)

__global__ __launch_bounds__(256, 1) void attn_kernel(
    const float* __restrict__ x,
    const float* __restrict__ Wq, const float* __restrict__ bq,
    const float* __restrict__ Wp, const float* __restrict__ bp,
    float* __restrict__ out)
{
    extern __shared__ char smem[];
    const u32 sb = smem_u32(smem);
    const int tid = threadIdx.x;
    const int wid = tid >> 5;
    const int l   = tid & 31;

    const int b = blockIdx.x >> 6;
    const int qbase = blockIdx.x * 256;

    // ---- stage: X (fp32->fp16), K, V, Wq, Wp; row stride 72 halves ----
    {
        const float4* xs = (const float4*)(x + (size_t)qbase * CH);
        #pragma unroll
        for (int it = 0; it < 16; it++) {
            int idx = tid + it * 256;
            int row = idx >> 4, c4 = idx & 15;
            float4 f = __ldg(xs + idx);
            __half2* d = (__half2*)(smem + SM_X + (row * 72 + c4 * 4) * 2);
            d[0] = __floats2half2_rn(f.x, f.y);
            d[1] = __floats2half2_rn(f.z, f.w);
        }
        const uint4* ks = (const uint4*)(g_kh + (size_t)b * NKV * CH);
        const uint4* vs = (const uint4*)(g_vh + (size_t)b * NKV * CH);
        #pragma unroll
        for (int it = 0; it < 8; it++) {
            int idx = tid + it * 256;
            int row = idx >> 3, sub = idx & 7;
            *(uint4*)(smem + SM_K + (row * 72 + sub * 8) * 2) = __ldg(ks + idx);
            *(uint4*)(smem + SM_V + (row * 72 + sub * 8) * 2) = __ldg(vs + idx);
        }
        #pragma unroll
        for (int it = 0; it < 8; it++) {
            int idx = tid + it * 256;
            int sel = idx >> 10;
            int r   = (idx >> 4) & 63, c4 = idx & 15;
            const float4* src = (const float4*)(sel ? Wp : Wq);
            float4 f = __ldg(src + (idx & 1023));
            __half2* d = (__half2*)(smem + (sel ? SM_WP : SM_WQ) + (r * 72 + c4 * 4) * 2);
            d[0] = __floats2half2_rn(f.x, f.y);
            d[1] = __floats2half2_rn(f.z, f.w);
        }
    }
    __syncthreads();

    const u32 offA  = (l & 15) * 144 + (l >> 4) * 16;
    const u32 offBk = ((l & 7) + (l >> 4) * 8) * 144 + ((l >> 3) & 1) * 16;
    const u32 offBt = ((l & 7) + ((l >> 3) & 1) * 8) * 144 + (l >> 4) * 16;

    const u32 aK  = sb + SM_K  + offBk;
    const u32 aV  = sb + SM_V  + offBt;
    const u32 aWQ = sb + SM_WQ + offBt;
    const u32 aWP = sb + SM_WP + offBt;

    // ---- GEMM1: Q = (X @ Wq + bq) * QSCALE for both rowgroups ----
    u32 aQ[2][4][4];
    #pragma unroll
    for (int rg = 0; rg < 2; rg++) {
        const u32 aX = sb + SM_X + (wid * 32 + rg * 16) * 144 + offA;
        u32 ax[4][4];
        #pragma unroll
        for (int kc = 0; kc < 4; kc++)
            ldsm4(ax[kc][0], ax[kc][1], ax[kc][2], ax[kc][3], aX + kc * 32);
        #pragma unroll
        for (int ng = 0; ng < 4; ng++) {
            float C0[4] = {0.f, 0.f, 0.f, 0.f};
            float C1[4] = {0.f, 0.f, 0.f, 0.f};
            #pragma unroll
            for (int kc = 0; kc < 4; kc++) {
                u32 b0, b1, b2, b3;
                ldsm4t(b0, b1, b2, b3, aWQ + kc * 16 * 144 + ng * 32);
                mma16816(C0, ax[kc], b0, b1);
                mma16816(C1, ax[kc], b2, b3);
            }
            int col0 = ng * 16 + (l & 3) * 2;
            float q00 = __ldg(bq + col0),     q01 = __ldg(bq + col0 + 1);
            float q10 = __ldg(bq + col0 + 8), q11 = __ldg(bq + col0 + 9);
            aQ[rg][ng][0] = pack_h2((C0[0] + q00) * QSCALE, (C0[1] + q01) * QSCALE);
            aQ[rg][ng][1] = pack_h2((C0[2] + q00) * QSCALE, (C0[3] + q01) * QSCALE);
            aQ[rg][ng][2] = pack_h2((C1[0] + q10) * QSCALE, (C1[1] + q11) * QSCALE);
            aQ[rg][ng][3] = pack_h2((C1[2] + q10) * QSCALE, (C1[3] + q11) * QSCALE);
        }
    }

    // ---- mainloop ----
    float O[2][8][4];
    #pragma unroll
    for (int rg = 0; rg < 2; rg++)
        #pragma unroll
        for (int m = 0; m < 8; m++)
            { O[rg][m][0] = 0.f; O[rg][m][1] = 0.f; O[rg][m][2] = 0.f; O[rg][m][3] = 0.f; }
    float ls[2][2] = {{0.f, 0.f}, {0.f, 0.f}};

    #pragma unroll 1
    for (int c = 0; c < 16; c++) {
        u32 kb[4][4];
        #pragma unroll
        for (int kc = 0; kc < 4; kc++)
            ldsm4(kb[kc][0], kb[kc][1], kb[kc][2], kb[kc][3],
                  aK + c * 16 * 144 + kc * 32);

        u32 pA[2][4];
        #pragma unroll
        for (int rg = 0; rg < 2; rg++) {
            float S0[4] = {0.f, 0.f, 0.f, 0.f};
            float S1[4] = {0.f, 0.f, 0.f, 0.f};
            #pragma unroll
            for (int kc = 0; kc < 4; kc++) {
                mma16816(S0, aQ[rg][kc], kb[kc][0], kb[kc][1]);
                mma16816(S1, aQ[rg][kc], kb[kc][2], kb[kc][3]);
            }
            pA[rg][0] = ex2_h2(pack_h2(S0[0], S0[1]));
            pA[rg][1] = ex2_h2(pack_h2(S0[2], S0[3]));
            pA[rg][2] = ex2_h2(pack_h2(S1[0], S1[1]));
            pA[rg][3] = ex2_h2(pack_h2(S1[2], S1[3]));
            __half2 s02 = __hadd2(*(__half2*)&pA[rg][0], *(__half2*)&pA[rg][2]);
            __half2 s13 = __hadd2(*(__half2*)&pA[rg][1], *(__half2*)&pA[rg][3]);
            float2 f0 = __half22float2(s02);
            float2 f1 = __half22float2(s13);
            ls[rg][0] += f0.x + f0.y;
            ls[rg][1] += f1.x + f1.y;
        }

        const u32 vbase = aV + c * 16 * 144;
        #pragma unroll
        for (int ng = 0; ng < 4; ng++) {
            u32 v0, v1, v2, v3;
            ldsm4t(v0, v1, v2, v3, vbase + ng * 32);
            #pragma unroll
            for (int rg = 0; rg < 2; rg++) {
                mma16816(O[rg][2 * ng],     pA[rg], v0, v1);
                mma16816(O[rg][2 * ng + 1], pA[rg], v2, v3);
            }
        }
    }

    // ---- per-rowgroup: normalize, GEMM4, store ----
    #pragma unroll
    for (int rg = 0; rg < 2; rg++) {
        float l0 = ls[rg][0], l1 = ls[rg][1];
        l0 += __shfl_xor_sync(0xffffffffu, l0, 1);
        l0 += __shfl_xor_sync(0xffffffffu, l0, 2);
        l1 += __shfl_xor_sync(0xffffffffu, l1, 1);
        l1 += __shfl_xor_sync(0xffffffffu, l1, 2);
        const float rl0 = 1.0f / l0;
        const float rl1 = 1.0f / l1;

        u32 aO[4][4];
        #pragma unroll
        for (int kc = 0; kc < 4; kc++) {
            aO[kc][0] = pack_h2(O[rg][2 * kc][0] * rl0,     O[rg][2 * kc][1] * rl0);
            aO[kc][1] = pack_h2(O[rg][2 * kc][2] * rl1,     O[rg][2 * kc][3] * rl1);
            aO[kc][2] = pack_h2(O[rg][2 * kc + 1][0] * rl0, O[rg][2 * kc + 1][1] * rl0);
            aO[kc][3] = pack_h2(O[rg][2 * kc + 1][2] * rl1, O[rg][2 * kc + 1][3] * rl1);
        }

        const int row0 = qbase + wid * 32 + rg * 16 + (l >> 2);
        #pragma unroll
        for (int ng = 0; ng < 4; ng++) {
            float C0[4] = {0.f, 0.f, 0.f, 0.f};
            float C1[4] = {0.f, 0.f, 0.f, 0.f};
            #pragma unroll
            for (int kc = 0; kc < 4; kc++) {
                u32 b0, b1, b2, b3;
                ldsm4t(b0, b1, b2, b3, aWP + kc * 16 * 144 + ng * 32);
                mma16816(C0, aO[kc], b0, b1);
                mma16816(C1, aO[kc], b2, b3);
            }
            int col0 = ng * 16 + (l & 3) * 2;
            float p00 = __ldg(bp + col0),     p01 = __ldg(bp + col0 + 1);
            float p10 = __ldg(bp + col0 + 8), p11 = __ldg(bp + col0 + 9);
            float2* o0 = (float2*)(out + (size_t)row0 * CH + col0);
            float2* o1 = (float2*)(out + (size_t)(row0 + 8) * CH + col0);
            o0[0] = make_float2(C0[0] + p00, C0[1] + p01);
            o0[4] = make_float2(C1[0] + p10, C1[1] + p11);
            o1[0] = make_float2(C0[2] + p00, C0[3] + p01);
            o1[4] = make_float2(C1[2] + p10, C1[3] + p11);
        }
    }
}

// ---------------------------------------------------------------------------
extern "C" void kernel_launch(void* const* d_in, const int* in_sizes, int n_in,
                              void* d_out, int out_size)
{
    const float* x     = (const float*)d_in[0];
    const float* Wq    = (const float*)d_in[1];
    const float* bq    = (const float*)d_in[2];
    const float* Wk    = (const float*)d_in[3];
    const float* bk    = (const float*)d_in[4];
    const float* Wv    = (const float*)d_in[5];
    const float* bv    = (const float*)d_in[6];
    const float* Wsr   = (const float*)d_in[7];
    const float* bsr   = (const float*)d_in[8];
    const float* gamma = (const float*)d_in[9];
    const float* beta  = (const float*)d_in[10];
    const float* Wp    = (const float*)d_in[11];
    const float* bp    = (const float*)d_in[12];
    float* out = (float*)d_out;

    int B = in_sizes[0] / (NQ * CH);
    if (B > MAXB) B = MAXB;

    cudaFuncSetAttribute(attn_kernel, cudaFuncAttributeMaxDynamicSharedMemorySize, SM_TOTAL);

    conv_kernel<<<B * 4 * CVSPLIT, 256, CV_SMEM>>>(x, Wsr);
    lnkv_kernel<<<B * 8, 256>>>(bsr, gamma, beta, Wk, bk, Wv, bv);
    attn_kernel<<<B * 64, 256, SM_TOTAL>>>(x, Wq, bq, Wp, bp, out);
}

// round 10
// speedup vs baseline: 7.8016x; 1.0488x over previous
#include <cuda_runtime.h>
#include <cuda_fp16.h>

#define NQ   16384
#define NKV  256
#define CH   64
#define MAXB 8
#define CVSPLIT 8

typedef unsigned long long u64;
typedef unsigned int u32;

__device__ __forceinline__ u32 pack_h2(float lo, float hi) {
    u32 r; asm("cvt.rn.f16x2.f32 %0, %1, %2;" : "=r"(r) : "f"(hi), "f"(lo)); return r;
}
__device__ __forceinline__ u32 smem_u32(const void* p) {
    u32 a; asm("{ .reg .u64 t; cvta.to.shared.u64 t, %1; cvt.u32.u64 %0, t; }" : "=r"(a) : "l"(p));
    return a;
}
__device__ __forceinline__ void ldsm4(u32& r0, u32& r1, u32& r2, u32& r3, u32 addr) {
    asm volatile("ldmatrix.sync.aligned.m8n8.x4.shared.b16 {%0,%1,%2,%3}, [%4];"
        : "=r"(r0), "=r"(r1), "=r"(r2), "=r"(r3) : "r"(addr));
}
__device__ __forceinline__ void ldsm4t(u32& r0, u32& r1, u32& r2, u32& r3, u32 addr) {
    asm volatile("ldmatrix.sync.aligned.m8n8.x4.trans.shared.b16 {%0,%1,%2,%3}, [%4];"
        : "=r"(r0), "=r"(r1), "=r"(r2), "=r"(r3) : "r"(addr));
}
__device__ __forceinline__ void mma16816(float* c, const u32* a, u32 b0, u32 b1) {
    asm volatile("mma.sync.aligned.m16n8k16.row.col.f32.f16.f16.f32 "
        "{%0,%1,%2,%3}, {%4,%5,%6,%7}, {%8,%9}, {%0,%1,%2,%3};"
        : "+f"(c[0]), "+f"(c[1]), "+f"(c[2]), "+f"(c[3])
        : "r"(a[0]), "r"(a[1]), "r"(a[2]), "r"(a[3]), "r"(b0), "r"(b1));
}
__device__ __forceinline__ u32 ex2_h2(u32 s) {
    u32 d; asm("ex2.approx.f16x2 %0, %1;" : "=r"(d) : "r"(s)); return d;
}

// Scratch (no cudaMalloc allowed)
__device__ float  g_part[CVSPLIT * MAXB * NKV * CH];  // conv partials (4MB)
__device__ __half g_kh [MAXB * NKV * CH];             // K fp16 [tok][ch]
__device__ __half g_vh [MAXB * NKV * CH];             // V fp16 [tok][ch]

// ---------------------------------------------------------------------------
// K1: conv via mma split-fp16 (3 terms). 32-token blocks, register prefetch.
// grid = 64 tiles x 8 splits = 512 blocks. 8 warps = 2 rowtiles x 4 co-groups.
// ---------------------------------------------------------------------------
#define CV_AHI 0
#define CV_ALO 4608
#define CV_WHI 9216
#define CV_WLO 18432
#define CV_SMEM 27648

__global__ __launch_bounds__(256) void conv_kernel(
    const float* __restrict__ x, const float* __restrict__ Wsr)
{
    extern __shared__ char smc[];
    const u32 sb = smem_u32(smc);
    const int tid = threadIdx.x;
    const int wid = tid >> 5;
    const int l   = tid & 31;
    const int rt  = wid >> 2;         // rowtile 0..1
    const int ngg = wid & 3;          // co group 0..3

    const int split = blockIdx.x & 7;       // kernel row i
    const int tile  = blockIdx.x >> 3;      // 0..63
    const int i     = split;

    const u32 offA  = (l & 15) * 144 + (l >> 4) * 16;
    const u32 offBt = ((l & 7) + ((l >> 3) & 1) * 8) * 144 + (l >> 4) * 16;

    float C[2][4] = {{0.f,0.f,0.f,0.f},{0.f,0.f,0.f,0.f}};

    // staging: 32 tokens x 64 ch; thread = token(tid>>3), 8 ch ((tid&7)*8)
    const int stok = tid >> 3;
    const int sch  = (tid & 7) * 8;
    const int gtok = tile * 32 + stok;
    const int b  = gtok >> 8;
    const int rm = gtok & 255;
    const int oh = rm >> 4, ow = rm & 15;
    const float4* xbase = (const float4*)(x +
        ((size_t)(b * 128 + oh * 8 + i) * 128 + ow * 8) * CH + sch);   // +16 f4/j
    const float4* wbase = (const float4*)(Wsr + (size_t)(i * 8) * 64 * 64); // +1024/j

    float4 pA0, pA1, pW[4];
    pA0 = __ldg(xbase);  pA1 = __ldg(xbase + 1);
    #pragma unroll
    for (int e = 0; e < 4; e++) pW[e] = __ldg(wbase + e * 256 + tid);

    #pragma unroll 1
    for (int j = 0; j < 8; j++) {
        // ---- convert & store current j ----
        {
            __half2 h01 = __floats2half2_rn(pA0.x, pA0.y);
            __half2 h23 = __floats2half2_rn(pA0.z, pA0.w);
            __half2 h45 = __floats2half2_rn(pA1.x, pA1.y);
            __half2 h67 = __floats2half2_rn(pA1.z, pA1.w);
            float2 b01 = __half22float2(h01), b23 = __half22float2(h23);
            float2 b45 = __half22float2(h45), b67 = __half22float2(h67);
            int o = (stok * 72 + sch) * 2;
            *(__half2*)(smc + CV_AHI + o)      = h01;
            *(__half2*)(smc + CV_AHI + o + 4)  = h23;
            *(__half2*)(smc + CV_AHI + o + 8)  = h45;
            *(__half2*)(smc + CV_AHI + o + 12) = h67;
            *(__half2*)(smc + CV_ALO + o)      = __floats2half2_rn(pA0.x - b01.x, pA0.y - b01.y);
            *(__half2*)(smc + CV_ALO + o + 4)  = __floats2half2_rn(pA0.z - b23.x, pA0.w - b23.y);
            *(__half2*)(smc + CV_ALO + o + 8)  = __floats2half2_rn(pA1.x - b45.x, pA1.y - b45.y);
            *(__half2*)(smc + CV_ALO + o + 12) = __floats2half2_rn(pA1.z - b67.x, pA1.w - b67.y);
        }
        #pragma unroll
        for (int e = 0; e < 4; e++) {
            int idx = e * 256 + tid;
            int row = idx >> 4, c4 = idx & 15;
            float4 f = pW[e];
            __half2 h01 = __floats2half2_rn(f.x, f.y);
            __half2 h23 = __floats2half2_rn(f.z, f.w);
            float2 b01 = __half22float2(h01), b23 = __half22float2(h23);
            int o = (row * 72 + c4 * 4) * 2;
            *(__half2*)(smc + CV_WHI + o)     = h01;
            *(__half2*)(smc + CV_WHI + o + 4) = h23;
            *(__half2*)(smc + CV_WLO + o)     = __floats2half2_rn(f.x - b01.x, f.y - b01.y);
            *(__half2*)(smc + CV_WLO + o + 4) = __floats2half2_rn(f.z - b23.x, f.w - b23.y);
        }
        __syncthreads();

        // ---- prefetch j+1 (overlaps mma) ----
        if (j < 7) {
            pA0 = __ldg(xbase + (j + 1) * 16);
            pA1 = __ldg(xbase + (j + 1) * 16 + 1);
            #pragma unroll
            for (int e = 0; e < 4; e++)
                pW[e] = __ldg(wbase + (j + 1) * 1024 + e * 256 + tid);
        }

        // ---- mma: 16 rows x 16 co per warp, 3 terms ----
        u32 axh[4][4], axl[4][4];
        #pragma unroll
        for (int kc = 0; kc < 4; kc++) {
            ldsm4(axh[kc][0], axh[kc][1], axh[kc][2], axh[kc][3],
                  sb + CV_AHI + rt * 16 * 144 + offA + kc * 32);
            ldsm4(axl[kc][0], axl[kc][1], axl[kc][2], axl[kc][3],
                  sb + CV_ALO + rt * 16 * 144 + offA + kc * 32);
        }
        #pragma unroll
        for (int kc = 0; kc < 4; kc++) {
            u32 h0, h1, h2, h3, q0, q1, q2, q3;
            ldsm4t(h0, h1, h2, h3, sb + CV_WHI + offBt + kc * 16 * 144 + ngg * 32);
            ldsm4t(q0, q1, q2, q3, sb + CV_WLO + offBt + kc * 16 * 144 + ngg * 32);
            mma16816(C[0], axh[kc], h0, h1);
            mma16816(C[1], axh[kc], h2, h3);
            mma16816(C[0], axl[kc], h0, h1);
            mma16816(C[1], axl[kc], h2, h3);
            mma16816(C[0], axh[kc], q0, q1);
            mma16816(C[1], axh[kc], q2, q3);
        }
        __syncthreads();
    }

    // ---- epilogue ----
    {
        int tl0 = rt * 16 + (l >> 2);
        int gt0 = tile * 32 + tl0;
        int gt1 = gt0 + 8;
        float* gp = g_part + (size_t)split * (MAXB * NKV * CH);
        int col0 = ngg * 16 + (l & 3) * 2;
        *(float2*)(gp + (size_t)gt0 * CH + col0)     = make_float2(C[0][0], C[0][1]);
        *(float2*)(gp + (size_t)gt0 * CH + col0 + 8) = make_float2(C[1][0], C[1][1]);
        *(float2*)(gp + (size_t)gt1 * CH + col0)     = make_float2(C[0][2], C[0][3]);
        *(float2*)(gp + (size_t)gt1 * CH + col0 + 8) = make_float2(C[1][2], C[1][3]);
    }
}

// ---------------------------------------------------------------------------
// K2: K-split reduce + bias + LayerNorm + K/V proj -> fp16 K, V (row-major).
// ---------------------------------------------------------------------------
__global__ __launch_bounds__(256) void lnkv_kernel(
    const float* __restrict__ bsr,
    const float* __restrict__ gamma, const float* __restrict__ beta,
    const float* __restrict__ Wk, const float* __restrict__ bk,
    const float* __restrict__ Wv, const float* __restrict__ bv)
{
    __shared__ float sA[32 * 65];
    const int tid = threadIdx.x;
    const int tokbase = blockIdx.x * 32;

    for (int idx = tid; idx < 2048; idx += 256) {
        size_t off = (size_t)tokbase * CH + idx;
        float v = bsr[idx & 63];
        #pragma unroll
        for (int s = 0; s < CVSPLIT; s++)
            v += g_part[(size_t)s * (MAXB * NKV * CH) + off];
        sA[(idx >> 6) * 65 + (idx & 63)] = v;
    }
    __syncthreads();

    if (tid < 32) {
        float* a = sA + tid * 65;
        float mu = 0.f;
        #pragma unroll
        for (int c = 0; c < 64; c++) mu += a[c];
        mu *= (1.0f / 64.0f);
        float var = 0.f;
        #pragma unroll
        for (int c = 0; c < 64; c++) { float d = a[c] - mu; var += d * d; }
        var *= (1.0f / 64.0f);
        float inv = rsqrtf(var + 1e-5f);
        #pragma unroll
        for (int c = 0; c < 64; c++)
            a[c] = (a[c] - mu) * inv * gamma[c] + beta[c];
    }
    __syncthreads();

    const int token = tid >> 3;
    const int c4b   = tid & 7;
    const float* ar = sA + token * 65;
    const float4* Wk4 = (const float4*)Wk;
    const float4* Wv4 = (const float4*)Wv;
    const int gtok = tokbase + token;
    #pragma unroll
    for (int of = 0; of < 2; of++) {
        int c4 = c4b + of * 8;
        float4 ka = ((const float4*)bk)[c4];
        float4 va = ((const float4*)bv)[c4];
        for (int j = 0; j < 64; j++) {
            float  av = ar[j];
            float4 wk = Wk4[j * 16 + c4];
            float4 wv = Wv4[j * 16 + c4];
            ka.x += av * wk.x; ka.y += av * wk.y; ka.z += av * wk.z; ka.w += av * wk.w;
            va.x += av * wv.x; va.y += av * wv.y; va.z += av * wv.z; va.w += av * wv.w;
        }
        __half2* kp = (__half2*)(g_kh + (size_t)gtok * CH + c4 * 4);
        kp[0] = __floats2half2_rn(ka.x, ka.y);
        kp[1] = __floats2half2_rn(ka.z, ka.w);
        __half2* vp = (__half2*)(g_vh + (size_t)gtok * CH + c4 * 4);
        vp[0] = __floats2half2_rn(va.x, va.y);
        vp[1] = __floats2half2_rn(va.z, va.w);
    }
}

// ---------------------------------------------------------------------------
// K3: mma fused attention; CTA = 128 queries, 8 warps. X loaded DIRECTLY from
// gmem into A-fragments (no smem X) -> smem 92KB -> 2 CTAs/SM.
// ---------------------------------------------------------------------------
#define SM_K    0            // K  [256][72] fp16  36864B
#define SM_V    36864        // V  [256][72] fp16  36864B
#define SM_WQ   73728        // Wq [64][72]  fp16  9216B
#define SM_WP   82944        // Wp [64][72]  fp16  9216B
#define SM_TOTAL 92160

#define QSCALE 0.1803368801f   // 0.125 * log2(e)

__global__ __launch_bounds__(256, 2) void attn_kernel(
    const float* __restrict__ x,
    const float* __restrict__ Wq, const float* __restrict__ bq,
    const float* __restrict__ Wp, const float* __restrict__ bp,
    float* __restrict__ out)
{
    extern __shared__ char smem[];
    const u32 sb = smem_u32(smem);
    const int tid = threadIdx.x;
    const int wid = tid >> 5;
    const int l   = tid & 31;
    const int wrow = wid * 16;

    const int b = blockIdx.x >> 7;
    const int qbase = blockIdx.x * 128;

    // ---- stage: K, V, Wq, Wp (row stride 72 halves) ----
    {
        const uint4* ks = (const uint4*)(g_kh + (size_t)b * NKV * CH);
        const uint4* vs = (const uint4*)(g_vh + (size_t)b * NKV * CH);
        #pragma unroll
        for (int it = 0; it < 8; it++) {
            int idx = tid + it * 256;
            int row = idx >> 3, sub = idx & 7;
            *(uint4*)(smem + SM_K + (row * 72 + sub * 8) * 2) = __ldg(ks + idx);
            *(uint4*)(smem + SM_V + (row * 72 + sub * 8) * 2) = __ldg(vs + idx);
        }
        #pragma unroll
        for (int it = 0; it < 8; it++) {
            int idx = tid + it * 256;
            int sel = idx >> 10;
            int r   = (idx >> 4) & 63, c4 = idx & 15;
            const float4* src = (const float4*)(sel ? Wp : Wq);
            float4 f = __ldg(src + (idx & 1023));
            __half2* d = (__half2*)(smem + (sel ? SM_WP : SM_WQ) + (r * 72 + c4 * 4) * 2);
            d[0] = __floats2half2_rn(f.x, f.y);
            d[1] = __floats2half2_rn(f.z, f.w);
        }
    }

    const u32 offA  = (l & 15) * 144 + (l >> 4) * 16;
    const u32 offBk = ((l & 7) + (l >> 4) * 8) * 144 + ((l >> 3) & 1) * 16;
    const u32 offBt = ((l & 7) + ((l >> 3) & 1) * 8) * 144 + (l >> 4) * 16;

    const u32 aK  = sb + SM_K  + offBk;
    const u32 aV  = sb + SM_V  + offBt;
    const u32 aWQ = sb + SM_WQ + offBt;
    const u32 aWP = sb + SM_WP + offBt;

    // ---- load X A-frags directly from gmem (fragment layout) ----
    u32 ax[4][4];
    {
        const int r0 = qbase + wrow + (l >> 2);
        const int c0 = (l & 3) * 2;
        const float* x0 = x + (size_t)r0 * CH + c0;
        const float* x1 = x + (size_t)(r0 + 8) * CH + c0;
        #pragma unroll
        for (int kc = 0; kc < 4; kc++) {
            float2 f00 = __ldg((const float2*)(x0 + kc * 16));
            float2 f10 = __ldg((const float2*)(x1 + kc * 16));
            float2 f01 = __ldg((const float2*)(x0 + kc * 16 + 8));
            float2 f11 = __ldg((const float2*)(x1 + kc * 16 + 8));
            ax[kc][0] = pack_h2(f00.x, f00.y);
            ax[kc][1] = pack_h2(f10.x, f10.y);
            ax[kc][2] = pack_h2(f01.x, f01.y);
            ax[kc][3] = pack_h2(f11.x, f11.y);
        }
    }
    __syncthreads();

    // ---- GEMM1: Q = (X @ Wq + bq) * QSCALE ----
    u32 aQ[4][4];
    #pragma unroll
    for (int ng = 0; ng < 4; ng++) {
        float C0[4] = {0.f, 0.f, 0.f, 0.f};
        float C1[4] = {0.f, 0.f, 0.f, 0.f};
        #pragma unroll
        for (int kc = 0; kc < 4; kc++) {
            u32 b0, b1, b2, b3;
            ldsm4t(b0, b1, b2, b3, aWQ + kc * 16 * 144 + ng * 32);
            mma16816(C0, ax[kc], b0, b1);
            mma16816(C1, ax[kc], b2, b3);
        }
        int col0 = ng * 16 + (l & 3) * 2;
        float q00 = __ldg(bq + col0),     q01 = __ldg(bq + col0 + 1);
        float q10 = __ldg(bq + col0 + 8), q11 = __ldg(bq + col0 + 9);
        aQ[ng][0] = pack_h2((C0[0] + q00) * QSCALE, (C0[1] + q01) * QSCALE);
        aQ[ng][1] = pack_h2((C0[2] + q00) * QSCALE, (C0[3] + q01) * QSCALE);
        aQ[ng][2] = pack_h2((C1[0] + q10) * QSCALE, (C1[1] + q11) * QSCALE);
        aQ[ng][3] = pack_h2((C1[2] + q10) * QSCALE, (C1[3] + q11) * QSCALE);
    }

    // ---- mainloop: P = 2^(Q@K^T) via ex2.f16x2, O += P@V ----
    float O[8][4];
    #pragma unroll
    for (int m = 0; m < 8; m++)
        { O[m][0] = 0.f; O[m][1] = 0.f; O[m][2] = 0.f; O[m][3] = 0.f; }
    float ls0 = 0.f, ls1 = 0.f;

    #pragma unroll 1
    for (int c = 0; c < 16; c++) {
        const u32 kbase = aK + c * 16 * 144;
        float S0[4] = {0.f, 0.f, 0.f, 0.f};
        float S1[4] = {0.f, 0.f, 0.f, 0.f};
        #pragma unroll
        for (int kc = 0; kc < 4; kc++) {
            u32 b0, b1, b2, b3;
            ldsm4(b0, b1, b2, b3, kbase + kc * 32);
            mma16816(S0, aQ[kc], b0, b1);
            mma16816(S1, aQ[kc], b2, b3);
        }
        u32 pA[4];
        pA[0] = ex2_h2(pack_h2(S0[0], S0[1]));
        pA[1] = ex2_h2(pack_h2(S0[2], S0[3]));
        pA[2] = ex2_h2(pack_h2(S1[0], S1[1]));
        pA[3] = ex2_h2(pack_h2(S1[2], S1[3]));
        {
            __half2 s02 = __hadd2(*(__half2*)&pA[0], *(__half2*)&pA[2]);
            __half2 s13 = __hadd2(*(__half2*)&pA[1], *(__half2*)&pA[3]);
            float2 f0 = __half22float2(s02);
            float2 f1 = __half22float2(s13);
            ls0 += f0.x + f0.y;
            ls1 += f1.x + f1.y;
        }
        const u32 vbase = aV + c * 16 * 144;
        #pragma unroll
        for (int ng = 0; ng < 4; ng++) {
            u32 v0, v1, v2, v3;
            ldsm4t(v0, v1, v2, v3, vbase + ng * 32);
            mma16816(O[2 * ng],     pA, v0, v1);
            mma16816(O[2 * ng + 1], pA, v2, v3);
        }
    }

    ls0 += __shfl_xor_sync(0xffffffffu, ls0, 1);
    ls0 += __shfl_xor_sync(0xffffffffu, ls0, 2);
    ls1 += __shfl_xor_sync(0xffffffffu, ls1, 1);
    ls1 += __shfl_xor_sync(0xffffffffu, ls1, 2);
    const float rl0 = 1.0f / ls0;
    const float rl1 = 1.0f / ls1;

    // ---- pack O (scaled) into A-frags ----
    u32 aO[4][4];
    #pragma unroll
    for (int kc = 0; kc < 4; kc++) {
        aO[kc][0] = pack_h2(O[2 * kc][0] * rl0,     O[2 * kc][1] * rl0);
        aO[kc][1] = pack_h2(O[2 * kc][2] * rl1,     O[2 * kc][3] * rl1);
        aO[kc][2] = pack_h2(O[2 * kc + 1][0] * rl0, O[2 * kc + 1][1] * rl0);
        aO[kc][3] = pack_h2(O[2 * kc + 1][2] * rl1, O[2 * kc + 1][3] * rl1);
    }

    // ---- GEMM4: Y = O @ Wp + bp -> gmem ----
    const int row0 = qbase + wrow + (l >> 2);
    #pragma unroll
    for (int ng = 0; ng < 4; ng++) {
        float C0[4] = {0.f, 0.f, 0.f, 0.f};
        float C1[4] = {0.f, 0.f, 0.f, 0.f};
        #pragma unroll
        for (int kc = 0; kc < 4; kc++) {
            u32 b0, b1, b2, b3;
            ldsm4t(b0, b1, b2, b3, aWP + kc * 16 * 144 + ng * 32);
            mma16816(C0, aO[kc], b0, b1);
            mma16816(C1, aO[kc], b2, b3);
        }
        int col0 = ng * 16 + (l & 3) * 2;
        float p00 = __ldg(bp + col0),     p01 = __ldg(bp + col0 + 1);
        float p10 = __ldg(bp + col0 + 8), p11 = __ldg(bp + col0 + 9);
        float2* o0 = (float2*)(out + (size_t)row0 * CH + col0);
        float2* o1 = (float2*)(out + (size_t)(row0 + 8) * CH + col0);
        o0[0] = make_float2(C0[0] + p00, C0[1] + p01);
        o0[4] = make_float2(C1[0] + p10, C1[1] + p11);
        o1[0] = make_float2(C0[2] + p00, C0[3] + p01);
        o1[4] = make_float2(C1[2] + p10, C1[3] + p11);
    }
}

// ---------------------------------------------------------------------------
extern "C" void kernel_launch(void* const* d_in, const int* in_sizes, int n_in,
                              void* d_out, int out_size)
{
    const float* x     = (const float*)d_in[0];
    const float* Wq    = (const float*)d_in[1];
    const float* bq    = (const float*)d_in[2];
    const float* Wk    = (const float*)d_in[3];
    const float* bk    = (const float*)d_in[4];
    const float* Wv    = (const float*)d_in[5];
    const float* bv    = (const float*)d_in[6];
    const float* Wsr   = (const float*)d_in[7];
    const float* bsr   = (const float*)d_in[8];
    const float* gamma = (const float*)d_in[9];
    const float* beta  = (const float*)d_in[10];
    const float* Wp    = (const float*)d_in[11];
    const float* bp    = (const float*)d_in[12];
    float* out = (float*)d_out;

    int B = in_sizes[0] / (NQ * CH);
    if (B > MAXB) B = MAXB;

    cudaFuncSetAttribute(attn_kernel, cudaFuncAttributeMaxDynamicSharedMemorySize, SM_TOTAL);

    conv_kernel<<<B * 8 * CVSPLIT, 256, CV_SMEM>>>(x, Wsr);
    lnkv_kernel<<<B * 8, 256>>>(bsr, gamma, beta, Wk, bk, Wv, bv);
    attn_kernel<<<B * 128, 256, SM_TOTAL>>>(x, Wq, bq, Wp, bp, out);
}

// round 11
// speedup vs baseline: 8.3059x; 1.0646x over previous
#include <cuda_runtime.h>
#include <cuda_fp16.h>

#define NQ   16384
#define NKV  256
#define CH   64
#define MAXB 8
#define CVSPLIT 8

typedef unsigned long long u64;
typedef unsigned int u32;

__device__ __forceinline__ u32 pack_h2(float lo, float hi) {
    u32 r; asm("cvt.rn.f16x2.f32 %0, %1, %2;" : "=r"(r) : "f"(hi), "f"(lo)); return r;
}
__device__ __forceinline__ u32 smem_u32(const void* p) {
    u32 a; asm("{ .reg .u64 t; cvta.to.shared.u64 t, %1; cvt.u32.u64 %0, t; }" : "=r"(a) : "l"(p));
    return a;
}
__device__ __forceinline__ void ldsm4(u32& r0, u32& r1, u32& r2, u32& r3, u32 addr) {
    asm volatile("ldmatrix.sync.aligned.m8n8.x4.shared.b16 {%0,%1,%2,%3}, [%4];"
        : "=r"(r0), "=r"(r1), "=r"(r2), "=r"(r3) : "r"(addr));
}
__device__ __forceinline__ void ldsm4t(u32& r0, u32& r1, u32& r2, u32& r3, u32 addr) {
    asm volatile("ldmatrix.sync.aligned.m8n8.x4.trans.shared.b16 {%0,%1,%2,%3}, [%4];"
        : "=r"(r0), "=r"(r1), "=r"(r2), "=r"(r3) : "r"(addr));
}
__device__ __forceinline__ void mma16816(float* c, const u32* a, u32 b0, u32 b1) {
    asm volatile("mma.sync.aligned.m16n8k16.row.col.f32.f16.f16.f32 "
        "{%0,%1,%2,%3}, {%4,%5,%6,%7}, {%8,%9}, {%0,%1,%2,%3};"
        : "+f"(c[0]), "+f"(c[1]), "+f"(c[2]), "+f"(c[3])
        : "r"(a[0]), "r"(a[1]), "r"(a[2]), "r"(a[3]), "r"(b0), "r"(b1));
}
__device__ __forceinline__ u32 ex2_h2(u32 s) {
    u32 d; asm("ex2.approx.f16x2 %0, %1;" : "=r"(d) : "r"(s)); return d;
}
#define CP_ASYNC16(sm, gp) \
    asm volatile("cp.async.cg.shared.global [%0], [%1], 16;" :: "r"(sm), "l"(gp) : "memory")
#define CP_COMMIT()  asm volatile("cp.async.commit_group;" ::: "memory")
#define CP_WAIT0()   asm volatile("cp.async.wait_group 0;" ::: "memory")

// Scratch (no cudaMalloc allowed)
__device__ float  g_part[CVSPLIT * MAXB * NKV * CH];  // conv partials (4MB)
__device__ __half g_kh [MAXB * NKV * CH];             // K fp16 [tok][ch]
__device__ __half g_vh [MAXB * NKV * CH];             // V fp16 [tok][ch]

// ---------------------------------------------------------------------------
// K1: conv via mma split-fp16 (3 terms), DOUBLE-BUFFERED smem, reg prefetch.
// grid = 64 tiles x 8 splits. 8 warps = 2 rowtiles x 4 co-groups.
// ---------------------------------------------------------------------------
#define CV_AHI 0
#define CV_ALO 4608
#define CV_WHI 9216
#define CV_WLO 18432
#define CV_BUF 27648
#define CV_SMEM (2 * CV_BUF)

__global__ __launch_bounds__(256) void conv_kernel(
    const float* __restrict__ x, const float* __restrict__ Wsr)
{
    extern __shared__ char smc[];
    const u32 sb = smem_u32(smc);
    const int tid = threadIdx.x;
    const int wid = tid >> 5;
    const int l   = tid & 31;
    const int rt  = wid >> 2;         // rowtile 0..1
    const int ngg = wid & 3;          // co group 0..3

    const int split = blockIdx.x & 7;       // kernel row i
    const int tile  = blockIdx.x >> 3;      // 0..63
    const int i     = split;

    const u32 offA  = (l & 15) * 144 + (l >> 4) * 16;
    const u32 offBt = ((l & 7) + ((l >> 3) & 1) * 8) * 144 + (l >> 4) * 16;

    float C[2][4] = {{0.f,0.f,0.f,0.f},{0.f,0.f,0.f,0.f}};

    const int stok = tid >> 3;
    const int sch  = (tid & 7) * 8;
    const int gtok = tile * 32 + stok;
    const int b  = gtok >> 8;
    const int rm = gtok & 255;
    const int oh = rm >> 4, ow = rm & 15;
    const float4* xbase = (const float4*)(x +
        ((size_t)(b * 128 + oh * 8 + i) * 128 + ow * 8) * CH + sch);
    const float4* wbase = (const float4*)(Wsr + (size_t)(i * 8) * 64 * 64);

    float4 pA0, pA1, pW[4];

    auto stage = [&](int bo) {
        __half2 h01 = __floats2half2_rn(pA0.x, pA0.y);
        __half2 h23 = __floats2half2_rn(pA0.z, pA0.w);
        __half2 h45 = __floats2half2_rn(pA1.x, pA1.y);
        __half2 h67 = __floats2half2_rn(pA1.z, pA1.w);
        float2 b01 = __half22float2(h01), b23 = __half22float2(h23);
        float2 b45 = __half22float2(h45), b67 = __half22float2(h67);
        int o = bo + (stok * 72 + sch) * 2;
        *(__half2*)(smc + CV_AHI + o)      = h01;
        *(__half2*)(smc + CV_AHI + o + 4)  = h23;
        *(__half2*)(smc + CV_AHI + o + 8)  = h45;
        *(__half2*)(smc + CV_AHI + o + 12) = h67;
        *(__half2*)(smc + CV_ALO + o)      = __floats2half2_rn(pA0.x - b01.x, pA0.y - b01.y);
        *(__half2*)(smc + CV_ALO + o + 4)  = __floats2half2_rn(pA0.z - b23.x, pA0.w - b23.y);
        *(__half2*)(smc + CV_ALO + o + 8)  = __floats2half2_rn(pA1.x - b45.x, pA1.y - b45.y);
        *(__half2*)(smc + CV_ALO + o + 12) = __floats2half2_rn(pA1.z - b67.x, pA1.w - b67.y);
        #pragma unroll
        for (int e = 0; e < 4; e++) {
            int idx = e * 256 + tid;
            int row = idx >> 4, c4 = idx & 15;
            float4 f = pW[e];
            __half2 w01 = __floats2half2_rn(f.x, f.y);
            __half2 w23 = __floats2half2_rn(f.z, f.w);
            float2 c01 = __half22float2(w01), c23 = __half22float2(w23);
            int o2 = bo + (row * 72 + c4 * 4) * 2;
            *(__half2*)(smc + CV_WHI + o2)     = w01;
            *(__half2*)(smc + CV_WHI + o2 + 4) = w23;
            *(__half2*)(smc + CV_WLO + o2)     = __floats2half2_rn(f.x - c01.x, f.y - c01.y);
            *(__half2*)(smc + CV_WLO + o2 + 4) = __floats2half2_rn(f.z - c23.x, f.w - c23.y);
        }
    };

    // prologue: prefetch + stage j = 0
    pA0 = __ldg(xbase); pA1 = __ldg(xbase + 1);
    #pragma unroll
    for (int e = 0; e < 4; e++) pW[e] = __ldg(wbase + e * 256 + tid);
    stage(0);
    __syncthreads();

    #pragma unroll 1
    for (int j = 0; j < 8; j++) {
        const int cur = (j & 1) * CV_BUF;

        // prefetch j+1 (LDG in flight during mma)
        if (j < 7) {
            pA0 = __ldg(xbase + (j + 1) * 16);
            pA1 = __ldg(xbase + (j + 1) * 16 + 1);
            #pragma unroll
            for (int e = 0; e < 4; e++)
                pW[e] = __ldg(wbase + (j + 1) * 1024 + e * 256 + tid);
        }

        // mma from current buffer
        u32 axh[4][4], axl[4][4];
        #pragma unroll
        for (int kc = 0; kc < 4; kc++) {
            ldsm4(axh[kc][0], axh[kc][1], axh[kc][2], axh[kc][3],
                  sb + cur + CV_AHI + rt * 16 * 144 + offA + kc * 32);
            ldsm4(axl[kc][0], axl[kc][1], axl[kc][2], axl[kc][3],
                  sb + cur + CV_ALO + rt * 16 * 144 + offA + kc * 32);
        }
        #pragma unroll
        for (int kc = 0; kc < 4; kc++) {
            u32 h0, h1, h2, h3, q0, q1, q2, q3;
            ldsm4t(h0, h1, h2, h3, sb + cur + CV_WHI + offBt + kc * 16 * 144 + ngg * 32);
            ldsm4t(q0, q1, q2, q3, sb + cur + CV_WLO + offBt + kc * 16 * 144 + ngg * 32);
            mma16816(C[0], axh[kc], h0, h1);
            mma16816(C[1], axh[kc], h2, h3);
            mma16816(C[0], axl[kc], h0, h1);
            mma16816(C[1], axl[kc], h2, h3);
            mma16816(C[0], axh[kc], q0, q1);
            mma16816(C[1], axh[kc], q2, q3);
        }

        // stage j+1 into the other buffer
        if (j < 7) stage(((j + 1) & 1) * CV_BUF);
        __syncthreads();
    }

    // epilogue
    {
        int tl0 = rt * 16 + (l >> 2);
        int gt0 = tile * 32 + tl0;
        int gt1 = gt0 + 8;
        float* gp = g_part + (size_t)split * (MAXB * NKV * CH);
        int col0 = ngg * 16 + (l & 3) * 2;
        *(float2*)(gp + (size_t)gt0 * CH + col0)     = make_float2(C[0][0], C[0][1]);
        *(float2*)(gp + (size_t)gt0 * CH + col0 + 8) = make_float2(C[1][0], C[1][1]);
        *(float2*)(gp + (size_t)gt1 * CH + col0)     = make_float2(C[0][2], C[0][3]);
        *(float2*)(gp + (size_t)gt1 * CH + col0 + 8) = make_float2(C[1][2], C[1][3]);
    }
}

// ---------------------------------------------------------------------------
// K2: K-split reduce + bias + LayerNorm + K/V proj. 128 blocks x 16 tokens;
// Wk/Wv staged in smem (LDS broadcast instead of per-thread LDG streams).
// ---------------------------------------------------------------------------
__global__ __launch_bounds__(256) void lnkv_kernel(
    const float* __restrict__ bsr,
    const float* __restrict__ gamma, const float* __restrict__ beta,
    const float* __restrict__ Wk, const float* __restrict__ bk,
    const float* __restrict__ Wv, const float* __restrict__ bv)
{
    __shared__ float sW[8192];      // Wk [0:4096), Wv [4096:8192)
    __shared__ float sA[16 * 65];
    const int tid = threadIdx.x;
    const int tokbase = blockIdx.x * 16;

    // stage Wk/Wv (2048 float4, 8 per thread)
    {
        float4* d = (float4*)sW;
        const float4* k4 = (const float4*)Wk;
        const float4* v4 = (const float4*)Wv;
        #pragma unroll
        for (int e = 0; e < 4; e++) d[e * 256 + tid] = __ldg(k4 + e * 256 + tid);
        #pragma unroll
        for (int e = 0; e < 4; e++) d[1024 + e * 256 + tid] = __ldg(v4 + e * 256 + tid);
    }
    // reduce splits + bias (16 tok x 64 ch = 256 float4, 1 per thread)
    {
        int row = tid >> 4, c4 = tid & 15;
        size_t off = ((size_t)(tokbase + row) * CH + c4 * 4) / 4;
        const float4* bb = (const float4*)bsr;
        float4 v = __ldg(bb + c4);
        #pragma unroll
        for (int s = 0; s < CVSPLIT; s++) {
            float4 p = *((const float4*)(g_part + (size_t)s * (MAXB * NKV * CH)) + off);
            v.x += p.x; v.y += p.y; v.z += p.z; v.w += p.w;
        }
        float* a = sA + row * 65 + c4 * 4;
        a[0] = v.x; a[1] = v.y; a[2] = v.z; a[3] = v.w;
    }
    __syncthreads();

    if (tid < 16) {
        float* a = sA + tid * 65;
        float mu = 0.f;
        #pragma unroll
        for (int c = 0; c < 64; c++) mu += a[c];
        mu *= (1.0f / 64.0f);
        float var = 0.f;
        #pragma unroll
        for (int c = 0; c < 64; c++) { float d = a[c] - mu; var += d * d; }
        var *= (1.0f / 64.0f);
        float inv = rsqrtf(var + 1e-5f);
        #pragma unroll
        for (int c = 0; c < 64; c++)
            a[c] = (a[c] - mu) * inv * __ldg(gamma + c) + __ldg(beta + c);
    }
    __syncthreads();

    // projection: thread = (token, c4); 4 K cols + 4 V cols
    {
        const int token = tid >> 4, c4 = tid & 15;
        const float* ar = sA + token * 65;
        const float4* Wk4 = (const float4*)sW;
        const float4* Wv4 = (const float4*)sW + 1024;
        float4 ka = __ldg((const float4*)bk + c4);
        float4 va = __ldg((const float4*)bv + c4);
        #pragma unroll 4
        for (int j = 0; j < 64; j++) {
            float  av = ar[j];
            float4 wk = Wk4[j * 16 + c4];
            float4 wv = Wv4[j * 16 + c4];
            ka.x += av * wk.x; ka.y += av * wk.y; ka.z += av * wk.z; ka.w += av * wk.w;
            va.x += av * wv.x; va.y += av * wv.y; va.z += av * wv.z; va.w += av * wv.w;
        }
        const int gtok = tokbase + token;
        __half2* kp = (__half2*)(g_kh + (size_t)gtok * CH + c4 * 4);
        kp[0] = __floats2half2_rn(ka.x, ka.y);
        kp[1] = __floats2half2_rn(ka.z, ka.w);
        __half2* vp = (__half2*)(g_vh + (size_t)gtok * CH + c4 * 4);
        vp[0] = __floats2half2_rn(va.x, va.y);
        vp[1] = __floats2half2_rn(va.z, va.w);
    }
}

// ---------------------------------------------------------------------------
// K3: mma fused attention; 128q/CTA, 8 warps, 2 CTAs/SM.
// cp.async K/V staging overlapped with GEMM1; V ldsm hoisted above S-mma.
// ---------------------------------------------------------------------------
#define SM_K    0            // K  [256][72] fp16  36864B
#define SM_V    36864        // V  [256][72] fp16  36864B
#define SM_WQ   73728        // Wq [64][72]  fp16  9216B
#define SM_WP   82944        // Wp [64][72]  fp16  9216B
#define SM_TOTAL 92160

#define QSCALE 0.1803368801f   // 0.125 * log2(e)

__global__ __launch_bounds__(256, 2) void attn_kernel(
    const float* __restrict__ x,
    const float* __restrict__ Wq, const float* __restrict__ bq,
    const float* __restrict__ Wp, const float* __restrict__ bp,
    float* __restrict__ out)
{
    extern __shared__ char smem[];
    const u32 sb = smem_u32(smem);
    const int tid = threadIdx.x;
    const int wid = tid >> 5;
    const int l   = tid & 31;
    const int wrow = wid * 16;

    const int b = blockIdx.x >> 7;
    const int qbase = blockIdx.x * 128;

    // ---- 1. issue cp.async for K/V (lands during GEMM1) ----
    {
        const __half* ks = g_kh + (size_t)b * NKV * CH;
        const __half* vs = g_vh + (size_t)b * NKV * CH;
        #pragma unroll
        for (int it = 0; it < 8; it++) {
            int idx = tid + it * 256;
            int row = idx >> 3, sub = idx & 7;
            u32 so = (row * 72 + sub * 8) * 2;
            CP_ASYNC16(sb + SM_K + so, ks + idx * 8);
            CP_ASYNC16(sb + SM_V + so, vs + idx * 8);
        }
        CP_COMMIT();
    }
    // ---- 2. stage Wq/Wp (fp32->fp16) ----
    {
        #pragma unroll
        for (int it = 0; it < 8; it++) {
            int idx = tid + it * 256;
            int sel = idx >> 10;
            int r   = (idx >> 4) & 63, c4 = idx & 15;
            const float4* src = (const float4*)(sel ? Wp : Wq);
            float4 f = __ldg(src + (idx & 1023));
            __half2* d = (__half2*)(smem + (sel ? SM_WP : SM_WQ) + (r * 72 + c4 * 4) * 2);
            d[0] = __floats2half2_rn(f.x, f.y);
            d[1] = __floats2half2_rn(f.z, f.w);
        }
    }

    const u32 offA  = (l & 15) * 144 + (l >> 4) * 16;
    const u32 offBk = ((l & 7) + (l >> 4) * 8) * 144 + ((l >> 3) & 1) * 16;
    const u32 offBt = ((l & 7) + ((l >> 3) & 1) * 8) * 144 + (l >> 4) * 16;

    const u32 aK  = sb + SM_K  + offBk;
    const u32 aV  = sb + SM_V  + offBt;
    const u32 aWQ = sb + SM_WQ + offBt;
    const u32 aWP = sb + SM_WP + offBt;

    // ---- 3. X A-frags direct from gmem ----
    u32 ax[4][4];
    {
        const int r0 = qbase + wrow + (l >> 2);
        const int c0 = (l & 3) * 2;
        const float* x0 = x + (size_t)r0 * CH + c0;
        const float* x1 = x + (size_t)(r0 + 8) * CH + c0;
        #pragma unroll
        for (int kc = 0; kc < 4; kc++) {
            float2 f00 = __ldg((const float2*)(x0 + kc * 16));
            float2 f10 = __ldg((const float2*)(x1 + kc * 16));
            float2 f01 = __ldg((const float2*)(x0 + kc * 16 + 8));
            float2 f11 = __ldg((const float2*)(x1 + kc * 16 + 8));
            ax[kc][0] = pack_h2(f00.x, f00.y);
            ax[kc][1] = pack_h2(f10.x, f10.y);
            ax[kc][2] = pack_h2(f01.x, f01.y);
            ax[kc][3] = pack_h2(f11.x, f11.y);
        }
    }
    __syncthreads();    // Wq/Wp visible (cp.async still in flight)

    // ---- 4. GEMM1: Q = (X @ Wq + bq) * QSCALE ----
    u32 aQ[4][4];
    #pragma unroll
    for (int ng = 0; ng < 4; ng++) {
        float C0[4] = {0.f, 0.f, 0.f, 0.f};
        float C1[4] = {0.f, 0.f, 0.f, 0.f};
        #pragma unroll
        for (int kc = 0; kc < 4; kc++) {
            u32 b0, b1, b2, b3;
            ldsm4t(b0, b1, b2, b3, aWQ + kc * 16 * 144 + ng * 32);
            mma16816(C0, ax[kc], b0, b1);
            mma16816(C1, ax[kc], b2, b3);
        }
        int col0 = ng * 16 + (l & 3) * 2;
        float q00 = __ldg(bq + col0),     q01 = __ldg(bq + col0 + 1);
        float q10 = __ldg(bq + col0 + 8), q11 = __ldg(bq + col0 + 9);
        aQ[ng][0] = pack_h2((C0[0] + q00) * QSCALE, (C0[1] + q01) * QSCALE);
        aQ[ng][1] = pack_h2((C0[2] + q00) * QSCALE, (C0[3] + q01) * QSCALE);
        aQ[ng][2] = pack_h2((C1[0] + q10) * QSCALE, (C1[1] + q11) * QSCALE);
        aQ[ng][3] = pack_h2((C1[2] + q10) * QSCALE, (C1[3] + q11) * QSCALE);
    }

    CP_WAIT0();
    __syncthreads();    // K/V visible

    // ---- 5. mainloop: V frags hoisted, P = 2^S via ex2.f16x2, O += P@V ----
    float O[8][4];
    #pragma unroll
    for (int m = 0; m < 8; m++)
        { O[m][0] = 0.f; O[m][1] = 0.f; O[m][2] = 0.f; O[m][3] = 0.f; }
    float ls0 = 0.f, ls1 = 0.f;

    #pragma unroll 1
    for (int c = 0; c < 16; c++) {
        const u32 kbase = aK + c * 16 * 144;
        const u32 vbase = aV + c * 16 * 144;
        u32 vb[4][4];
        #pragma unroll
        for (int ng = 0; ng < 4; ng++)
            ldsm4t(vb[ng][0], vb[ng][1], vb[ng][2], vb[ng][3], vbase + ng * 32);

        float S0[4] = {0.f, 0.f, 0.f, 0.f};
        float S1[4] = {0.f, 0.f, 0.f, 0.f};
        #pragma unroll
        for (int kc = 0; kc < 4; kc++) {
            u32 b0, b1, b2, b3;
            ldsm4(b0, b1, b2, b3, kbase + kc * 32);
            mma16816(S0, aQ[kc], b0, b1);
            mma16816(S1, aQ[kc], b2, b3);
        }
        u32 pA[4];
        pA[0] = ex2_h2(pack_h2(S0[0], S0[1]));
        pA[1] = ex2_h2(pack_h2(S0[2], S0[3]));
        pA[2] = ex2_h2(pack_h2(S1[0], S1[1]));
        pA[3] = ex2_h2(pack_h2(S1[2], S1[3]));
        {
            __half2 s02 = __hadd2(*(__half2*)&pA[0], *(__half2*)&pA[2]);
            __half2 s13 = __hadd2(*(__half2*)&pA[1], *(__half2*)&pA[3]);
            float2 f0 = __half22float2(s02);
            float2 f1 = __half22float2(s13);
            ls0 += f0.x + f0.y;
            ls1 += f1.x + f1.y;
        }
        #pragma unroll
        for (int ng = 0; ng < 4; ng++) {
            mma16816(O[2 * ng],     pA, vb[ng][0], vb[ng][1]);
            mma16816(O[2 * ng + 1], pA, vb[ng][2], vb[ng][3]);
        }
    }

    ls0 += __shfl_xor_sync(0xffffffffu, ls0, 1);
    ls0 += __shfl_xor_sync(0xffffffffu, ls0, 2);
    ls1 += __shfl_xor_sync(0xffffffffu, ls1, 1);
    ls1 += __shfl_xor_sync(0xffffffffu, ls1, 2);
    const float rl0 = 1.0f / ls0;
    const float rl1 = 1.0f / ls1;

    // ---- pack O (scaled) into A-frags ----
    u32 aO[4][4];
    #pragma unroll
    for (int kc = 0; kc < 4; kc++) {
        aO[kc][0] = pack_h2(O[2 * kc][0] * rl0,     O[2 * kc][1] * rl0);
        aO[kc][1] = pack_h2(O[2 * kc][2] * rl1,     O[2 * kc][3] * rl1);
        aO[kc][2] = pack_h2(O[2 * kc + 1][0] * rl0, O[2 * kc + 1][1] * rl0);
        aO[kc][3] = pack_h2(O[2 * kc + 1][2] * rl1, O[2 * kc + 1][3] * rl1);
    }

    // ---- GEMM4: Y = O @ Wp + bp -> gmem ----
    const int row0 = qbase + wrow + (l >> 2);
    #pragma unroll
    for (int ng = 0; ng < 4; ng++) {
        float C0[4] = {0.f, 0.f, 0.f, 0.f};
        float C1[4] = {0.f, 0.f, 0.f, 0.f};
        #pragma unroll
        for (int kc = 0; kc < 4; kc++) {
            u32 b0, b1, b2, b3;
            ldsm4t(b0, b1, b2, b3, aWP + kc * 16 * 144 + ng * 32);
            mma16816(C0, aO[kc], b0, b1);
            mma16816(C1, aO[kc], b2, b3);
        }
        int col0 = ng * 16 + (l & 3) * 2;
        float p00 = __ldg(bp + col0),     p01 = __ldg(bp + col0 + 1);
        float p10 = __ldg(bp + col0 + 8), p11 = __ldg(bp + col0 + 9);
        float2* o0 = (float2*)(out + (size_t)row0 * CH + col0);
        float2* o1 = (float2*)(out + (size_t)(row0 + 8) * CH + col0);
        o0[0] = make_float2(C0[0] + p00, C0[1] + p01);
        o0[4] = make_float2(C1[0] + p10, C1[1] + p11);
        o1[0] = make_float2(C0[2] + p00, C0[3] + p01);
        o1[4] = make_float2(C1[2] + p10, C1[3] + p11);
    }
}

// ---------------------------------------------------------------------------
extern "C" void kernel_launch(void* const* d_in, const int* in_sizes, int n_in,
                              void* d_out, int out_size)
{
    const float* x     = (const float*)d_in[0];
    const float* Wq    = (const float*)d_in[1];
    const float* bq    = (const float*)d_in[2];
    const float* Wk    = (const float*)d_in[3];
    const float* bk    = (const float*)d_in[4];
    const float* Wv    = (const float*)d_in[5];
    const float* bv    = (const float*)d_in[6];
    const float* Wsr   = (const float*)d_in[7];
    const float* bsr   = (const float*)d_in[8];
    const float* gamma = (const float*)d_in[9];
    const float* beta  = (const float*)d_in[10];
    const float* Wp    = (const float*)d_in[11];
    const float* bp    = (const float*)d_in[12];
    float* out = (float*)d_out;

    int B = in_sizes[0] / (NQ * CH);
    if (B > MAXB) B = MAXB;

    cudaFuncSetAttribute(conv_kernel, cudaFuncAttributeMaxDynamicSharedMemorySize, CV_SMEM);
    cudaFuncSetAttribute(attn_kernel, cudaFuncAttributeMaxDynamicSharedMemorySize, SM_TOTAL);

    conv_kernel<<<B * 8 * CVSPLIT, 256, CV_SMEM>>>(x, Wsr);
    lnkv_kernel<<<B * 16, 256>>>(bsr, gamma, beta, Wk, bk, Wv, bv);
    attn_kernel<<<B * 128, 256, SM_TOTAL>>>(x, Wq, bq, Wp, bp, out);
}